// round 5
// baseline (speedup 1.0000x reference)
#include <cuda_runtime.h>
#include <cuda_bf16.h>
#include <math.h>
#include <stdint.h>

#define NUM_LAYERS 4
#define N_NODES 50000
#define N_PAD   50048            // 391 * 128
#define N_EDGES 800000
#define IN_FEAT 256
#define HIDDEN  512
#define MTILES  391

// ---------------- CSR scratch ----------------
__device__ int g_deg[N_NODES];
__device__ int g_row_ptr[N_NODES + 1];
__device__ int g_wptr[N_NODES];
__device__ int g_col[N_EDGES];

// ---------------- bf16 split operand buffers ----------------
__device__ __align__(16) __nv_bfloat16 g_xh[(size_t)N_PAD * IN_FEAT];
__device__ __align__(16) __nv_bfloat16 g_xl[(size_t)N_PAD * IN_FEAT];
__device__ __align__(16) __nv_bfloat16 g_agh[(size_t)NUM_LAYERS * N_PAD * HIDDEN];
__device__ __align__(16) __nv_bfloat16 g_agl[(size_t)NUM_LAYERS * N_PAD * HIDDEN];
__device__ __align__(16) __nv_bfloat16 g_o1h[(size_t)N_PAD * HIDDEN];
__device__ __align__(16) __nv_bfloat16 g_o1l[(size_t)N_PAD * HIDDEN];
__device__ __align__(16) __nv_bfloat16 g_o2h[(size_t)N_PAD * HIDDEN];
__device__ __align__(16) __nv_bfloat16 g_o2l[(size_t)N_PAD * HIDDEN];
#define W1_ELEMS (131072 + 3 * 262144)
#define W2_ELEMS (4 * 262144)
__device__ __align__(16) __nv_bfloat16 g_w1h[W1_ELEMS];
__device__ __align__(16) __nv_bfloat16 g_w1l[W1_ELEMS];
__device__ __align__(16) __nv_bfloat16 g_w2h[W2_ELEMS];
__device__ __align__(16) __nv_bfloat16 g_w2l[W2_ELEMS];

// ---------------- helpers ----------------
__device__ __forceinline__ uint32_t smem_u32(const void* p) {
    uint32_t a;
    asm("{ .reg .u64 t; cvta.to.shared.u64 t, %1; cvt.u32.u64 %0, t; }"
        : "=r"(a) : "l"(p));
    return a;
}

__device__ __forceinline__ void cpa16(uint32_t dst, const void* src) {
    asm volatile("cp.async.cg.shared.global [%0], [%1], 16;"
                 :: "r"(dst), "l"(src) : "memory");
}
#define CP_COMMIT() asm volatile("cp.async.commit_group;" ::: "memory")
#define CP_WAIT(n)  asm volatile("cp.async.wait_group %0;" :: "n"(n) : "memory")

#define LDSM4(r0, r1, r2, r3, addr)                                            \
    asm volatile("ldmatrix.sync.aligned.m8n8.x4.shared.b16 {%0,%1,%2,%3}, [%4];" \
                 : "=r"(r0), "=r"(r1), "=r"(r2), "=r"(r3) : "r"(addr))

#define MMA16816(c, a0, a1, a2, a3, b0, b1)                                    \
    asm volatile("mma.sync.aligned.m16n8k16.row.col.f32.bf16.bf16.f32 "        \
                 "{%0,%1,%2,%3},{%4,%5,%6,%7},{%8,%9},{%0,%1,%2,%3};"          \
                 : "+f"((c)[0]), "+f"((c)[1]), "+f"((c)[2]), "+f"((c)[3])      \
                 : "r"(a0), "r"(a1), "r"(a2), "r"(a3), "r"(b0), "r"(b1))

__device__ __forceinline__ void split_bf16(float v, __nv_bfloat16& h, __nv_bfloat16& l) {
    h = __float2bfloat16_rn(v);
    l = __float2bfloat16_rn(v - __bfloat162float(h));
}

// ================= CSR build =================
__global__ void k_zero_deg() {
    for (int i = blockIdx.x * blockDim.x + threadIdx.x; i < N_NODES;
         i += gridDim.x * blockDim.x)
        g_deg[i] = 0;
}

__global__ void k_hist(const int* __restrict__ ei) {
    int e = blockIdx.x * blockDim.x + threadIdx.x;
    if (e < N_EDGES) {
        int dst = ei[N_EDGES + e];
        if ((unsigned)dst < (unsigned)N_NODES) atomicAdd(&g_deg[dst], 1);
    }
}

__global__ void k_scan() {
    __shared__ int buf[1024];
    int t = threadIdx.x;
    int carry = 0;
    for (int base = 0; base < N_NODES; base += 1024) {
        int i = base + t;
        int v = (i < N_NODES) ? g_deg[i] : 0;
        buf[t] = v;
        __syncthreads();
#pragma unroll
        for (int off = 1; off < 1024; off <<= 1) {
            int tmp = (t >= off) ? buf[t - off] : 0;
            __syncthreads();
            buf[t] += tmp;
            __syncthreads();
        }
        int incl = buf[t];
        if (i < N_NODES) {
            g_row_ptr[i + 1] = carry + incl;
            g_wptr[i]        = carry + incl - v;
        }
        carry += buf[1023];
        __syncthreads();
    }
    if (t == 0) g_row_ptr[0] = 0;
}

__global__ void k_scatter(const int* __restrict__ ei) {
    int e = blockIdx.x * blockDim.x + threadIdx.x;
    if (e < N_EDGES) {
        int src = ei[e];
        int dst = ei[N_EDGES + e];
        if ((unsigned)dst < (unsigned)N_NODES && (unsigned)src < (unsigned)N_NODES) {
            int pos = atomicAdd(&g_wptr[dst], 1);
            g_col[pos] = src;
        }
    }
}

// ================= conversions =================
__global__ void k_convert_x(const float* __restrict__ x) {
    const int groups = N_PAD * IN_FEAT / 4;
    for (int g = blockIdx.x * blockDim.x + threadIdx.x; g < groups;
         g += gridDim.x * blockDim.x) {
        int e = g * 4;
        int m = e / IN_FEAT;
        float4 v = make_float4(0.f, 0.f, 0.f, 0.f);
        if (m < N_NODES) v = *(const float4*)&x[e];
        __nv_bfloat16 h0, h1, h2, h3, l0, l1, l2, l3;
        split_bf16(v.x, h0, l0); split_bf16(v.y, h1, l1);
        split_bf16(v.z, h2, l2); split_bf16(v.w, h3, l3);
        *(__nv_bfloat162*)&g_xh[e]     = __halves2bfloat162(h0, h1);
        *(__nv_bfloat162*)&g_xh[e + 2] = __halves2bfloat162(h2, h3);
        *(__nv_bfloat162*)&g_xl[e]     = __halves2bfloat162(l0, l1);
        *(__nv_bfloat162*)&g_xl[e + 2] = __halves2bfloat162(l2, l3);
    }
}

__global__ void k_convert_w(const float* __restrict__ Wi0,
                            const float* __restrict__ Wi_rest,
                            const float* __restrict__ Wr) {
    for (int g = blockIdx.x * blockDim.x + threadIdx.x; g < W1_ELEMS / 4;
         g += gridDim.x * blockDim.x) {
        int e = g * 4;
        float4 v = (e < 131072) ? *(const float4*)&Wi0[e]
                                : *(const float4*)&Wi_rest[e - 131072];
        __nv_bfloat16 h0, h1, h2, h3, l0, l1, l2, l3;
        split_bf16(v.x, h0, l0); split_bf16(v.y, h1, l1);
        split_bf16(v.z, h2, l2); split_bf16(v.w, h3, l3);
        *(__nv_bfloat162*)&g_w1h[e]     = __halves2bfloat162(h0, h1);
        *(__nv_bfloat162*)&g_w1h[e + 2] = __halves2bfloat162(h2, h3);
        *(__nv_bfloat162*)&g_w1l[e]     = __halves2bfloat162(l0, l1);
        *(__nv_bfloat162*)&g_w1l[e + 2] = __halves2bfloat162(l2, l3);
    }
    for (int g = blockIdx.x * blockDim.x + threadIdx.x; g < W2_ELEMS / 4;
         g += gridDim.x * blockDim.x) {
        int e = g * 4;
        float4 v = *(const float4*)&Wr[e];
        __nv_bfloat16 h0, h1, h2, h3, l0, l1, l2, l3;
        split_bf16(v.x, h0, l0); split_bf16(v.y, h1, l1);
        split_bf16(v.z, h2, l2); split_bf16(v.w, h3, l3);
        *(__nv_bfloat162*)&g_w2h[e]     = __halves2bfloat162(h0, h1);
        *(__nv_bfloat162*)&g_w2h[e + 2] = __halves2bfloat162(h2, h3);
        *(__nv_bfloat162*)&g_w2l[e]     = __halves2bfloat162(l0, l1);
        *(__nv_bfloat162*)&g_w2l[e + 2] = __halves2bfloat162(l2, l3);
    }
}

// ================= aggregation (one layer) -> bf16 hi/lo =================
__global__ void k_aggr(const float* __restrict__ states, int layer) {
    int node = blockIdx.x;      // 0..N_PAD-1
    int t    = threadIdx.x;     // 0..127, one float4 column each

    float4 acc = make_float4(0.f, 0.f, 0.f, 0.f);
    if (node < N_NODES) {
        const float4* S = (const float4*)(states + (size_t)layer * N_NODES * HIDDEN);
        int beg = g_row_ptr[node];
        int end = g_row_ptr[node + 1];
        for (int e = beg; e < end; e++) {
            int src = g_col[e];
            float4 v = S[(size_t)src * (HIDDEN / 4) + t];
            acc.x += v.x; acc.y += v.y; acc.z += v.z; acc.w += v.w;
        }
    }
    size_t o = ((size_t)layer * N_PAD + node) * HIDDEN + t * 4;
    __nv_bfloat16 h0, h1, h2, h3, l0, l1, l2, l3;
    split_bf16(acc.x, h0, l0); split_bf16(acc.y, h1, l1);
    split_bf16(acc.z, h2, l2); split_bf16(acc.w, h3, l3);
    *(__nv_bfloat162*)&g_agh[o]     = __halves2bfloat162(h0, h1);
    *(__nv_bfloat162*)&g_agh[o + 2] = __halves2bfloat162(h2, h3);
    *(__nv_bfloat162*)&g_agl[o]     = __halves2bfloat162(l0, l1);
    *(__nv_bfloat162*)&g_agl[o + 2] = __halves2bfloat162(l2, l3);
}

// ================= mma.sync dual-GEMM + tanh epilogue =================
// CTA tile 128(M) x 128(N) x 32(K); 8 warps in 2(M) x 4(N); warp tile 64x32.
// 3-stage cp.async pipeline, one __syncthreads per chunk.
#define ROWP 40
#define TE   (128 * ROWP)              // elems per tile = 5120
#define STAGE_E (4 * TE)               // elems per stage = 20480
#define NSTAGE 3
#define SMEM_BYTES (NSTAGE * STAGE_E * 2)   // 122880 B

__device__ __forceinline__ void load_stage(
    uint32_t sbase,
    const __nv_bfloat16* __restrict__ Ah, const __nv_bfloat16* __restrict__ Al,
    const __nv_bfloat16* __restrict__ Bh, const __nv_bfloat16* __restrict__ Bl,
    int bm, int n0, int kof, int astr, int bstr, int tid)
{
#pragma unroll
    for (int j = 0; j < 2; j++) {
        int idx = tid + j * 256;   // 0..511
        int r = idx >> 2;
        int c = idx & 3;
        uint32_t d = sbase + (uint32_t)(r * ROWP + c * 8) * 2;
        size_t ga = (size_t)(bm + r) * astr + kof + c * 8;
        size_t gb = (size_t)(n0 + r) * bstr + kof + c * 8;
        cpa16(d,              Ah + ga);
        cpa16(d + TE * 2,     Al + ga);
        cpa16(d + 2 * TE * 2, Bh + gb);
        cpa16(d + 3 * TE * 2, Bl + gb);
    }
}

__global__ __launch_bounds__(256)
void k_gemm_mma(int layer, int K1, int c1,
                const float* __restrict__ s_old,
                const float* __restrict__ leak,
                float* __restrict__ outp,
                int asel, int osel)
{
    extern __shared__ __nv_bfloat16 smem[];
    const uint32_t sm0 = smem_u32(smem);

    const int tid  = threadIdx.x;
    const int wid  = tid >> 5;
    const int lane = tid & 31;
    const int wm   = wid & 1;       // 0..1 (M)
    const int wn   = wid >> 1;      // 0..3 (N)
    const int bm   = blockIdx.y * 128;
    const int n0   = blockIdx.x * 128;

    // operand pointers from selectors
    const __nv_bfloat16 *a1h, *a1l;
    if (asel == 0)      { a1h = g_xh;  a1l = g_xl;  }
    else if (asel == 1) { a1h = g_o1h; a1l = g_o1l; }
    else                { a1h = g_o2h; a1l = g_o2l; }
    __nv_bfloat16 *oh = nullptr, *ol = nullptr;
    if (osel == 1)      { oh = g_o1h; ol = g_o1l; }
    else if (osel == 2) { oh = g_o2h; ol = g_o2l; }
    const __nv_bfloat16* a2h = g_agh + (size_t)layer * N_PAD * HIDDEN;
    const __nv_bfloat16* a2l = g_agl + (size_t)layer * N_PAD * HIDDEN;
    const size_t w1off = (layer == 0) ? 0 : (size_t)131072 + (size_t)(layer - 1) * 262144;
    const __nv_bfloat16* b1h = g_w1h + w1off;
    const __nv_bfloat16* b1l = g_w1l + w1off;
    const __nv_bfloat16* b2h = g_w2h + (size_t)layer * 262144;
    const __nv_bfloat16* b2l = g_w2l + (size_t)layer * 262144;

    float acc[4][4][4];
#pragma unroll
    for (int i = 0; i < 4; i++)
#pragma unroll
        for (int j = 0; j < 4; j++)
#pragma unroll
            for (int q = 0; q < 4; q++) acc[i][j][q] = 0.f;

    const int ctot = c1 + 16;

    // prologue: stages 0 and 1
#pragma unroll
    for (int p = 0; p < 2; p++) {
        uint32_t sb = sm0 + (uint32_t)(p * STAGE_E) * 2;
        if (p < c1)
            load_stage(sb, a1h, a1l, b1h, b1l, bm, n0, p * 32, K1, K1, tid);
        else
            load_stage(sb, a2h, a2l, b2h, b2l, bm, n0, (p - c1) * 32,
                       HIDDEN, HIDDEN, tid);
        CP_COMMIT();
    }

    // ldmatrix lane-address components
    const int arow = (lane & 7) + ((lane >> 3) & 1) * 8;   // + wm*64 + mi*16
    const int acol = (lane >> 4) * 8;                       // + ks*16
    const int brow = (lane & 7) + (lane >> 4) * 8;          // + wn*32 + ng2*16
    const int bcol = ((lane >> 3) & 1) * 8;                 // + ks*16

    int stage = 0;
    for (int ci = 0; ci < ctot; ci++) {
        CP_WAIT(1);            // group ci complete (ci+1 may be in flight)
        __syncthreads();       // also: all threads done reading stage (ci-1)%3

        // prefetch chunk ci+2 into stage (ci+2)%3 == (ci-1)%3
        if (ci + 2 < ctot) {
            int cj = ci + 2;
            int sj = stage + 2; if (sj >= NSTAGE) sj -= NSTAGE;
            uint32_t sb = sm0 + (uint32_t)(sj * STAGE_E) * 2;
            if (cj < c1)
                load_stage(sb, a1h, a1l, b1h, b1l, bm, n0, cj * 32, K1, K1, tid);
            else
                load_stage(sb, a2h, a2l, b2h, b2l, bm, n0, (cj - c1) * 32,
                           HIDDEN, HIDDEN, tid);
        }
        CP_COMMIT();           // commit even if empty to keep group counting uniform

        const uint32_t sb = sm0 + (uint32_t)(stage * STAGE_E) * 2;
        const uint32_t aB = sb + (uint32_t)((wm * 64 + arow) * ROWP + acol) * 2;
        const uint32_t bB = sb + (uint32_t)(2 * TE + (wn * 32 + brow) * ROWP + bcol) * 2;

#pragma unroll
        for (int ks = 0; ks < 2; ks++) {
            uint32_t ah[4][4], al[4][4], bh[4][2], bl[4][2];
#pragma unroll
            for (int mi = 0; mi < 4; mi++) {
                uint32_t ad = aB + (uint32_t)(mi * 16 * ROWP + ks * 16) * 2;
                LDSM4(ah[mi][0], ah[mi][1], ah[mi][2], ah[mi][3], ad);
                LDSM4(al[mi][0], al[mi][1], al[mi][2], al[mi][3], ad + TE * 2);
            }
#pragma unroll
            for (int g2 = 0; g2 < 2; g2++) {
                uint32_t bd = bB + (uint32_t)(g2 * 16 * ROWP + ks * 16) * 2;
                uint32_t t0, t1, t2, t3;
                LDSM4(t0, t1, t2, t3, bd);
                bh[2 * g2][0] = t0; bh[2 * g2][1] = t1;
                bh[2 * g2 + 1][0] = t2; bh[2 * g2 + 1][1] = t3;
                LDSM4(t0, t1, t2, t3, bd + TE * 2);
                bl[2 * g2][0] = t0; bl[2 * g2][1] = t1;
                bl[2 * g2 + 1][0] = t2; bl[2 * g2 + 1][1] = t3;
            }
#pragma unroll
            for (int mi = 0; mi < 4; mi++)
#pragma unroll
                for (int ni = 0; ni < 4; ni++) {
                    MMA16816(acc[mi][ni], ah[mi][0], ah[mi][1], ah[mi][2], ah[mi][3],
                             bh[ni][0], bh[ni][1]);
                    MMA16816(acc[mi][ni], ah[mi][0], ah[mi][1], ah[mi][2], ah[mi][3],
                             bl[ni][0], bl[ni][1]);
                    MMA16816(acc[mi][ni], al[mi][0], al[mi][1], al[mi][2], al[mi][3],
                             bh[ni][0], bh[ni][1]);
                }
        }
        if (++stage == NSTAGE) stage = 0;
    }

    // ---------------- epilogue ----------------
    const float a   = leak[0];
    const float oma = 1.0f - a;
#pragma unroll
    for (int mi = 0; mi < 4; mi++) {
#pragma unroll
        for (int h = 0; h < 2; h++) {
            int mm = bm + wm * 64 + mi * 16 + (lane >> 2) + h * 8;
            bool valid = (mm < N_NODES);
            size_t rowb = (size_t)mm * HIDDEN + n0 + wn * 32 + (lane & 3) * 2;
#pragma unroll
            for (int ni = 0; ni < 4; ni++) {
                size_t off = rowb + ni * 8;
                if (valid) {
                    float c0 = acc[mi][ni][2 * h];
                    float c1 = acc[mi][ni][2 * h + 1];
                    float2 s = *(const float2*)&s_old[off];
                    float o0 = a * tanhf(c0) + oma * s.x;
                    float o1 = a * tanhf(c1) + oma * s.y;
                    *(float2*)&outp[off] = make_float2(o0, o1);
                    if (oh) {
                        __nv_bfloat16 h0, h1, l0, l1;
                        split_bf16(o0, h0, l0);
                        split_bf16(o1, h1, l1);
                        *(__nv_bfloat162*)&oh[off] = __halves2bfloat162(h0, h1);
                        *(__nv_bfloat162*)&ol[off] = __halves2bfloat162(l0, l1);
                    }
                } else if (oh) {
                    __nv_bfloat162 z =
                        __halves2bfloat162(__float2bfloat16_rn(0.f),
                                           __float2bfloat16_rn(0.f));
                    *(__nv_bfloat162*)&oh[off] = z;
                    *(__nv_bfloat162*)&ol[off] = z;
                }
            }
        }
    }
}

// ================= launch =================
extern "C" void kernel_launch(void* const* d_in, const int* in_sizes, int n_in,
                              void* d_out, int out_size)
{
    const int*   ei      = (const int*)d_in[0];       // [2, E] int32
    const float* x       = (const float*)d_in[1];     // [N, 256]
    const float* states  = (const float*)d_in[2];     // [4, N, 512]
    const float* Wi0     = (const float*)d_in[3];     // [512, 256]
    const float* Wi_rest = (const float*)d_in[4];     // [3, 512, 512]
    const float* Wr      = (const float*)d_in[5];     // [4, 512, 512]
    const float* leak    = (const float*)d_in[6];     // [1]
    float*       out     = (float*)d_out;             // [4, N, 512]

    (void)in_sizes; (void)n_in; (void)out_size;

    // one-time setup: smem carveout + side stream + events (host objects only;
    // no device memory is allocated)
    static cudaStream_t sAg = nullptr;
    static cudaEvent_t evCsr = nullptr;
    static cudaEvent_t evA[NUM_LAYERS];
    if (sAg == nullptr) {
        cudaFuncSetAttribute(k_gemm_mma,
                             cudaFuncAttributeMaxDynamicSharedMemorySize,
                             SMEM_BYTES);
        cudaStreamCreateWithFlags(&sAg, cudaStreamNonBlocking);
        cudaEventCreateWithFlags(&evCsr, cudaEventDisableTiming);
        for (int l = 0; l < NUM_LAYERS; l++)
            cudaEventCreateWithFlags(&evA[l], cudaEventDisableTiming);
    }

    // ---- main stream: CSR build ----
    k_zero_deg<<<128, 256>>>();
    k_hist<<<(N_EDGES + 255) / 256, 256>>>(ei);
    k_scan<<<1, 1024>>>();
    k_scatter<<<(N_EDGES + 255) / 256, 256>>>(ei);
    cudaEventRecord(evCsr, 0);

    // ---- side stream: 4 layer aggregations (depend only on CSR + states) ----
    cudaStreamWaitEvent(sAg, evCsr, 0);
    for (int l = 0; l < NUM_LAYERS; l++) {
        k_aggr<<<N_PAD, 128, 0, sAg>>>(states, l);
        cudaEventRecord(evA[l], sAg);
    }

    // ---- main stream: conversions (overlap with aggregation) ----
    k_convert_x<<<4096, 256>>>(x);
    k_convert_w<<<1024, 256>>>(Wi0, Wi_rest, Wr);

    // ---- main stream: sequential GEMM chain; GEMM l waits on aggr l ----
    dim3 grid(HIDDEN / 128, MTILES);
    const int asel[4] = {0, 1, 2, 1};
    const int osel[4] = {1, 2, 1, 0};
    for (int l = 0; l < NUM_LAYERS; l++) {
        int K1 = (l == 0) ? IN_FEAT : HIDDEN;
        int c1 = K1 / 32;
        const float* so = states + (size_t)l * N_NODES * HIDDEN;
        float*       ol = out + (size_t)l * N_NODES * HIDDEN;
        cudaStreamWaitEvent(0, evA[l], 0);
        k_gemm_mma<<<grid, 256, SMEM_BYTES>>>(l, K1, c1, so, leak, ol,
                                              asel[l], osel[l]);
    }
}

// round 7
// speedup vs baseline: 1.1800x; 1.1800x over previous
#include <cuda_runtime.h>
#include <cuda_bf16.h>
#include <math.h>
#include <stdint.h>

#define NUM_LAYERS 4
#define N_NODES 50000
#define N_PAD   50048            // 391 * 128
#define N_EDGES 800000
#define IN_FEAT 256
#define HIDDEN  512
#define MTILES  391

// ---------------- CSR scratch ----------------
__device__ int g_deg[N_NODES];
__device__ int g_row_ptr[N_NODES + 1];
__device__ int g_wptr[N_NODES];
__device__ int g_col[N_EDGES];

// ---------------- bf16 split operand buffers ----------------
__device__ __align__(16) __nv_bfloat16 g_xh[(size_t)N_PAD * IN_FEAT];
__device__ __align__(16) __nv_bfloat16 g_xl[(size_t)N_PAD * IN_FEAT];
__device__ __align__(16) __nv_bfloat16 g_agh[(size_t)NUM_LAYERS * N_PAD * HIDDEN];
__device__ __align__(16) __nv_bfloat16 g_agl[(size_t)NUM_LAYERS * N_PAD * HIDDEN];
__device__ __align__(16) __nv_bfloat16 g_o1h[(size_t)N_PAD * HIDDEN];
__device__ __align__(16) __nv_bfloat16 g_o1l[(size_t)N_PAD * HIDDEN];
__device__ __align__(16) __nv_bfloat16 g_o2h[(size_t)N_PAD * HIDDEN];
__device__ __align__(16) __nv_bfloat16 g_o2l[(size_t)N_PAD * HIDDEN];
#define W1_ELEMS (131072 + 3 * 262144)
#define W2_ELEMS (4 * 262144)
__device__ __align__(16) __nv_bfloat16 g_w1h[W1_ELEMS];
__device__ __align__(16) __nv_bfloat16 g_w1l[W1_ELEMS];
__device__ __align__(16) __nv_bfloat16 g_w2h[W2_ELEMS];
__device__ __align__(16) __nv_bfloat16 g_w2l[W2_ELEMS];

// ---------------- helpers ----------------
__device__ __forceinline__ uint32_t smem_u32(const void* p) {
    uint32_t a;
    asm("{ .reg .u64 t; cvta.to.shared.u64 t, %1; cvt.u32.u64 %0, t; }"
        : "=r"(a) : "l"(p));
    return a;
}

__device__ __forceinline__ void cpa16(uint32_t dst, const void* src) {
    asm volatile("cp.async.cg.shared.global [%0], [%1], 16;"
                 :: "r"(dst), "l"(src) : "memory");
}
#define CP_COMMIT() asm volatile("cp.async.commit_group;" ::: "memory")
#define CP_WAIT(n)  asm volatile("cp.async.wait_group %0;" :: "n"(n) : "memory")

#define LDSM4(r0, r1, r2, r3, addr)                                            \
    asm volatile("ldmatrix.sync.aligned.m8n8.x4.shared.b16 {%0,%1,%2,%3}, [%4];" \
                 : "=r"(r0), "=r"(r1), "=r"(r2), "=r"(r3) : "r"(addr))

#define MMA16816(c, a0, a1, a2, a3, b0, b1)                                    \
    asm volatile("mma.sync.aligned.m16n8k16.row.col.f32.bf16.bf16.f32 "        \
                 "{%0,%1,%2,%3},{%4,%5,%6,%7},{%8,%9},{%0,%1,%2,%3};"          \
                 : "+f"((c)[0]), "+f"((c)[1]), "+f"((c)[2]), "+f"((c)[3])      \
                 : "r"(a0), "r"(a1), "r"(a2), "r"(a3), "r"(b0), "r"(b1))

__device__ __forceinline__ void split_bf16(float v, __nv_bfloat16& h, __nv_bfloat16& l) {
    h = __float2bfloat16_rn(v);
    l = __float2bfloat16_rn(v - __bfloat162float(h));
}

// ================= CSR build =================
__global__ void k_zero_deg() {
    for (int i = blockIdx.x * blockDim.x + threadIdx.x; i < N_NODES;
         i += gridDim.x * blockDim.x)
        g_deg[i] = 0;
}

__global__ void k_hist(const int* __restrict__ ei) {
    int e = blockIdx.x * blockDim.x + threadIdx.x;
    if (e < N_EDGES) {
        int dst = ei[N_EDGES + e];
        if ((unsigned)dst < (unsigned)N_NODES) atomicAdd(&g_deg[dst], 1);
    }
}

__global__ void k_scan() {
    __shared__ int buf[1024];
    int t = threadIdx.x;
    int carry = 0;
    for (int base = 0; base < N_NODES; base += 1024) {
        int i = base + t;
        int v = (i < N_NODES) ? g_deg[i] : 0;
        buf[t] = v;
        __syncthreads();
#pragma unroll
        for (int off = 1; off < 1024; off <<= 1) {
            int tmp = (t >= off) ? buf[t - off] : 0;
            __syncthreads();
            buf[t] += tmp;
            __syncthreads();
        }
        int incl = buf[t];
        if (i < N_NODES) {
            g_row_ptr[i + 1] = carry + incl;
            g_wptr[i]        = carry + incl - v;
        }
        carry += buf[1023];
        __syncthreads();
    }
    if (t == 0) g_row_ptr[0] = 0;
}

__global__ void k_scatter(const int* __restrict__ ei) {
    int e = blockIdx.x * blockDim.x + threadIdx.x;
    if (e < N_EDGES) {
        int src = ei[e];
        int dst = ei[N_EDGES + e];
        if ((unsigned)dst < (unsigned)N_NODES && (unsigned)src < (unsigned)N_NODES) {
            int pos = atomicAdd(&g_wptr[dst], 1);
            g_col[pos] = src;
        }
    }
}

// ================= conversions =================
__global__ void k_convert_x(const float* __restrict__ x) {
    const int groups = N_PAD * IN_FEAT / 4;
    for (int g = blockIdx.x * blockDim.x + threadIdx.x; g < groups;
         g += gridDim.x * blockDim.x) {
        int e = g * 4;
        int m = e / IN_FEAT;
        float4 v = make_float4(0.f, 0.f, 0.f, 0.f);
        if (m < N_NODES) v = *(const float4*)&x[e];
        __nv_bfloat16 h0, h1, h2, h3, l0, l1, l2, l3;
        split_bf16(v.x, h0, l0); split_bf16(v.y, h1, l1);
        split_bf16(v.z, h2, l2); split_bf16(v.w, h3, l3);
        *(__nv_bfloat162*)&g_xh[e]     = __halves2bfloat162(h0, h1);
        *(__nv_bfloat162*)&g_xh[e + 2] = __halves2bfloat162(h2, h3);
        *(__nv_bfloat162*)&g_xl[e]     = __halves2bfloat162(l0, l1);
        *(__nv_bfloat162*)&g_xl[e + 2] = __halves2bfloat162(l2, l3);
    }
}

__global__ void k_convert_w(const float* __restrict__ Wi0,
                            const float* __restrict__ Wi_rest,
                            const float* __restrict__ Wr) {
    for (int g = blockIdx.x * blockDim.x + threadIdx.x; g < W1_ELEMS / 4;
         g += gridDim.x * blockDim.x) {
        int e = g * 4;
        float4 v = (e < 131072) ? *(const float4*)&Wi0[e]
                                : *(const float4*)&Wi_rest[e - 131072];
        __nv_bfloat16 h0, h1, h2, h3, l0, l1, l2, l3;
        split_bf16(v.x, h0, l0); split_bf16(v.y, h1, l1);
        split_bf16(v.z, h2, l2); split_bf16(v.w, h3, l3);
        *(__nv_bfloat162*)&g_w1h[e]     = __halves2bfloat162(h0, h1);
        *(__nv_bfloat162*)&g_w1h[e + 2] = __halves2bfloat162(h2, h3);
        *(__nv_bfloat162*)&g_w1l[e]     = __halves2bfloat162(l0, l1);
        *(__nv_bfloat162*)&g_w1l[e + 2] = __halves2bfloat162(l2, l3);
    }
    for (int g = blockIdx.x * blockDim.x + threadIdx.x; g < W2_ELEMS / 4;
         g += gridDim.x * blockDim.x) {
        int e = g * 4;
        float4 v = *(const float4*)&Wr[e];
        __nv_bfloat16 h0, h1, h2, h3, l0, l1, l2, l3;
        split_bf16(v.x, h0, l0); split_bf16(v.y, h1, l1);
        split_bf16(v.z, h2, l2); split_bf16(v.w, h3, l3);
        *(__nv_bfloat162*)&g_w2h[e]     = __halves2bfloat162(h0, h1);
        *(__nv_bfloat162*)&g_w2h[e + 2] = __halves2bfloat162(h2, h3);
        *(__nv_bfloat162*)&g_w2l[e]     = __halves2bfloat162(l0, l1);
        *(__nv_bfloat162*)&g_w2l[e + 2] = __halves2bfloat162(l2, l3);
    }
}

// ================= aggregation (one layer) -> bf16 hi/lo =================
__global__ void k_aggr(const float* __restrict__ states, int layer) {
    int node = blockIdx.x;      // 0..N_PAD-1
    int t    = threadIdx.x;     // 0..127, one float4 column each

    float4 acc = make_float4(0.f, 0.f, 0.f, 0.f);
    if (node < N_NODES) {
        const float4* S = (const float4*)(states + (size_t)layer * N_NODES * HIDDEN);
        int beg = g_row_ptr[node];
        int end = g_row_ptr[node + 1];
        for (int e = beg; e < end; e++) {
            int src = g_col[e];
            float4 v = S[(size_t)src * (HIDDEN / 4) + t];
            acc.x += v.x; acc.y += v.y; acc.z += v.z; acc.w += v.w;
        }
    }
    size_t o = ((size_t)layer * N_PAD + node) * HIDDEN + t * 4;
    __nv_bfloat16 h0, h1, h2, h3, l0, l1, l2, l3;
    split_bf16(acc.x, h0, l0); split_bf16(acc.y, h1, l1);
    split_bf16(acc.z, h2, l2); split_bf16(acc.w, h3, l3);
    *(__nv_bfloat162*)&g_agh[o]     = __halves2bfloat162(h0, h1);
    *(__nv_bfloat162*)&g_agh[o + 2] = __halves2bfloat162(h2, h3);
    *(__nv_bfloat162*)&g_agl[o]     = __halves2bfloat162(l0, l1);
    *(__nv_bfloat162*)&g_agl[o + 2] = __halves2bfloat162(l2, l3);
}

// ================= mma.sync dual-GEMM + tanh epilogue =================
// CTA tile 128(M) x 128(N) x 32(K); 8 warps in 2(M) x 4(N); warp tile 64x32.
// 2-stage cp.async double buffer => 81920 B SMEM => 2 CTAs/SM (proven config).
#define ROWP 40
#define TE   (128 * ROWP)              // elems per tile = 5120
#define STAGE_E (4 * TE)               // elems per stage = 20480
#define SMEM_BYTES (2 * STAGE_E * 2)   // 81920 B

__device__ __forceinline__ void load_stage(
    uint32_t sbase,
    const __nv_bfloat16* __restrict__ Ah, const __nv_bfloat16* __restrict__ Al,
    const __nv_bfloat16* __restrict__ Bh, const __nv_bfloat16* __restrict__ Bl,
    int bm, int n0, int kof, int astr, int bstr, int tid)
{
#pragma unroll
    for (int j = 0; j < 2; j++) {
        int idx = tid + j * 256;   // 0..511
        int r = idx >> 2;
        int c = idx & 3;
        uint32_t d = sbase + (uint32_t)(r * ROWP + c * 8) * 2;
        size_t ga = (size_t)(bm + r) * astr + kof + c * 8;
        size_t gb = (size_t)(n0 + r) * bstr + kof + c * 8;
        cpa16(d,              Ah + ga);
        cpa16(d + TE * 2,     Al + ga);
        cpa16(d + 2 * TE * 2, Bh + gb);
        cpa16(d + 3 * TE * 2, Bl + gb);
    }
}

__global__ __launch_bounds__(256)
void k_gemm_mma(int layer, int K1, int c1,
                const float* __restrict__ s_old,
                const float* __restrict__ leak,
                float* __restrict__ outp,
                int asel, int osel)
{
    extern __shared__ __nv_bfloat16 smem[];
    const uint32_t sm0 = smem_u32(smem);

    const int tid  = threadIdx.x;
    const int wid  = tid >> 5;
    const int lane = tid & 31;
    const int wm   = wid & 1;       // 0..1 (M)
    const int wn   = wid >> 1;      // 0..3 (N)
    const int bm   = blockIdx.y * 128;
    const int n0   = blockIdx.x * 128;

    // operand pointers from selectors
    const __nv_bfloat16 *a1h, *a1l;
    if (asel == 0)      { a1h = g_xh;  a1l = g_xl;  }
    else if (asel == 1) { a1h = g_o1h; a1l = g_o1l; }
    else                { a1h = g_o2h; a1l = g_o2l; }
    __nv_bfloat16 *oh = nullptr, *ol = nullptr;
    if (osel == 1)      { oh = g_o1h; ol = g_o1l; }
    else if (osel == 2) { oh = g_o2h; ol = g_o2l; }
    const __nv_bfloat16* a2h = g_agh + (size_t)layer * N_PAD * HIDDEN;
    const __nv_bfloat16* a2l = g_agl + (size_t)layer * N_PAD * HIDDEN;
    const size_t w1off = (layer == 0) ? 0 : (size_t)131072 + (size_t)(layer - 1) * 262144;
    const __nv_bfloat16* b1h = g_w1h + w1off;
    const __nv_bfloat16* b1l = g_w1l + w1off;
    const __nv_bfloat16* b2h = g_w2h + (size_t)layer * 262144;
    const __nv_bfloat16* b2l = g_w2l + (size_t)layer * 262144;

    float acc[4][4][4];
#pragma unroll
    for (int i = 0; i < 4; i++)
#pragma unroll
        for (int j = 0; j < 4; j++)
#pragma unroll
            for (int q = 0; q < 4; q++) acc[i][j][q] = 0.f;

    const int ctot = c1 + 16;

    // prologue: stage 0 = phase-1 chunk 0
    load_stage(sm0, a1h, a1l, b1h, b1l, bm, n0, 0, K1, K1, tid);
    CP_COMMIT();

    // ldmatrix lane-address components
    const int arow = (lane & 7) + ((lane >> 3) & 1) * 8;   // + wm*64 + mi*16
    const int acol = (lane >> 4) * 8;                       // + ks*16
    const int brow = (lane & 7) + (lane >> 4) * 8;          // + wn*32 + ng2*16
    const int bcol = ((lane >> 3) & 1) * 8;                 // + ks*16

    for (int ci = 0; ci < ctot; ci++) {
        if (ci + 1 < ctot) {
            int cj = ci + 1;
            uint32_t sb = sm0 + (uint32_t)((cj & 1) * STAGE_E) * 2;
            if (cj < c1)
                load_stage(sb, a1h, a1l, b1h, b1l, bm, n0, cj * 32, K1, K1, tid);
            else
                load_stage(sb, a2h, a2l, b2h, b2l, bm, n0, (cj - c1) * 32,
                           HIDDEN, HIDDEN, tid);
            CP_COMMIT();
            CP_WAIT(1);
        } else {
            CP_WAIT(0);
        }
        __syncthreads();

        const uint32_t sb = sm0 + (uint32_t)((ci & 1) * STAGE_E) * 2;
        const uint32_t aB = sb + (uint32_t)((wm * 64 + arow) * ROWP + acol) * 2;
        const uint32_t bB = sb + (uint32_t)(2 * TE + (wn * 32 + brow) * ROWP + bcol) * 2;

#pragma unroll
        for (int ks = 0; ks < 2; ks++) {
            uint32_t ah[4][4], al[4][4], bh[4][2], bl[4][2];
#pragma unroll
            for (int mi = 0; mi < 4; mi++) {
                uint32_t ad = aB + (uint32_t)(mi * 16 * ROWP + ks * 16) * 2;
                LDSM4(ah[mi][0], ah[mi][1], ah[mi][2], ah[mi][3], ad);
                LDSM4(al[mi][0], al[mi][1], al[mi][2], al[mi][3], ad + TE * 2);
            }
#pragma unroll
            for (int g2 = 0; g2 < 2; g2++) {
                uint32_t bd = bB + (uint32_t)(g2 * 16 * ROWP + ks * 16) * 2;
                uint32_t t0, t1, t2, t3;
                LDSM4(t0, t1, t2, t3, bd);
                bh[2 * g2][0] = t0; bh[2 * g2][1] = t1;
                bh[2 * g2 + 1][0] = t2; bh[2 * g2 + 1][1] = t3;
                LDSM4(t0, t1, t2, t3, bd + TE * 2);
                bl[2 * g2][0] = t0; bl[2 * g2][1] = t1;
                bl[2 * g2 + 1][0] = t2; bl[2 * g2 + 1][1] = t3;
            }
#pragma unroll
            for (int mi = 0; mi < 4; mi++)
#pragma unroll
                for (int ni = 0; ni < 4; ni++) {
                    MMA16816(acc[mi][ni], ah[mi][0], ah[mi][1], ah[mi][2], ah[mi][3],
                             bh[ni][0], bh[ni][1]);
                    MMA16816(acc[mi][ni], ah[mi][0], ah[mi][1], ah[mi][2], ah[mi][3],
                             bl[ni][0], bl[ni][1]);
                    MMA16816(acc[mi][ni], al[mi][0], al[mi][1], al[mi][2], al[mi][3],
                             bh[ni][0], bh[ni][1]);
                }
        }
        __syncthreads();
    }

    // ---------------- epilogue ----------------
    const float a   = leak[0];
    const float oma = 1.0f - a;
#pragma unroll
    for (int mi = 0; mi < 4; mi++) {
#pragma unroll
        for (int h = 0; h < 2; h++) {
            int mm = bm + wm * 64 + mi * 16 + (lane >> 2) + h * 8;
            bool valid = (mm < N_NODES);
            size_t rowb = (size_t)mm * HIDDEN + n0 + wn * 32 + (lane & 3) * 2;
#pragma unroll
            for (int ni = 0; ni < 4; ni++) {
                size_t off = rowb + ni * 8;
                if (valid) {
                    float c0 = acc[mi][ni][2 * h];
                    float c1 = acc[mi][ni][2 * h + 1];
                    float2 s = *(const float2*)&s_old[off];
                    float o0 = a * tanhf(c0) + oma * s.x;
                    float o1 = a * tanhf(c1) + oma * s.y;
                    *(float2*)&outp[off] = make_float2(o0, o1);
                    if (oh) {
                        __nv_bfloat16 h0, h1, l0, l1;
                        split_bf16(o0, h0, l0);
                        split_bf16(o1, h1, l1);
                        *(__nv_bfloat162*)&oh[off] = __halves2bfloat162(h0, h1);
                        *(__nv_bfloat162*)&ol[off] = __halves2bfloat162(l0, l1);
                    }
                } else if (oh) {
                    __nv_bfloat162 z =
                        __halves2bfloat162(__float2bfloat16_rn(0.f),
                                           __float2bfloat16_rn(0.f));
                    *(__nv_bfloat162*)&oh[off] = z;
                    *(__nv_bfloat162*)&ol[off] = z;
                }
            }
        }
    }
}

// ================= launch =================
extern "C" void kernel_launch(void* const* d_in, const int* in_sizes, int n_in,
                              void* d_out, int out_size)
{
    const int*   ei      = (const int*)d_in[0];       // [2, E] int32
    const float* x       = (const float*)d_in[1];     // [N, 256]
    const float* states  = (const float*)d_in[2];     // [4, N, 512]
    const float* Wi0     = (const float*)d_in[3];     // [512, 256]
    const float* Wi_rest = (const float*)d_in[4];     // [3, 512, 512]
    const float* Wr      = (const float*)d_in[5];     // [4, 512, 512]
    const float* leak    = (const float*)d_in[6];     // [1]
    float*       out     = (float*)d_out;             // [4, N, 512]

    (void)in_sizes; (void)n_in; (void)out_size;

    // one-time setup: smem carveout + side stream + events (host objects only;
    // no device memory is allocated)
    static cudaStream_t sAg = nullptr;
    static cudaEvent_t evFork = nullptr;
    static cudaEvent_t evA[NUM_LAYERS];
    if (sAg == nullptr) {
        cudaFuncSetAttribute(k_gemm_mma,
                             cudaFuncAttributeMaxDynamicSharedMemorySize,
                             SMEM_BYTES);
        cudaStreamCreateWithFlags(&sAg, cudaStreamNonBlocking);
        cudaEventCreateWithFlags(&evFork, cudaEventDisableTiming);
        for (int l = 0; l < NUM_LAYERS; l++)
            cudaEventCreateWithFlags(&evA[l], cudaEventDisableTiming);
    }

    // ---- fork the side stream FROM the capture-origin stream (stream 0) ----
    // (a non-origin stream may only enter the capture via an event recorded
    //  in the captured stream — this is what round 6 got wrong)
    cudaEventRecord(evFork, 0);
    cudaStreamWaitEvent(sAg, evFork, 0);

    // ---- side stream: CSR build + 4 layer aggregations ----
    k_zero_deg<<<128, 256, 0, sAg>>>();
    k_hist<<<(N_EDGES + 255) / 256, 256, 0, sAg>>>(ei);
    k_scan<<<1, 1024, 0, sAg>>>();
    k_scatter<<<(N_EDGES + 255) / 256, 256, 0, sAg>>>(ei);
    for (int l = 0; l < NUM_LAYERS; l++) {
        k_aggr<<<N_PAD, 128, 0, sAg>>>(states, l);
        cudaEventRecord(evA[l], sAg);
    }

    // ---- main stream: conversions (overlap with CSR + aggregation) ----
    k_convert_x<<<4096, 256>>>(x);
    k_convert_w<<<1024, 256>>>(Wi0, Wi_rest, Wr);

    // ---- main stream: sequential GEMM chain; GEMM l waits on aggr l ----
    dim3 grid(HIDDEN / 128, MTILES);
    const int asel[4] = {0, 1, 2, 1};
    const int osel[4] = {1, 2, 1, 0};
    for (int l = 0; l < NUM_LAYERS; l++) {
        int K1 = (l == 0) ? IN_FEAT : HIDDEN;
        int c1 = K1 / 32;
        const float* so = states + (size_t)l * N_NODES * HIDDEN;
        float*       ol = out + (size_t)l * N_NODES * HIDDEN;
        cudaStreamWaitEvent(0, evA[l], 0);
        k_gemm_mma<<<grid, 256, SMEM_BYTES>>>(l, K1, c1, so, leak, ol,
                                              asel[l], osel[l]);
    }
}

// round 8
// speedup vs baseline: 1.1863x; 1.0053x over previous
#include <cuda_runtime.h>
#include <cuda_bf16.h>
#include <math.h>
#include <stdint.h>

#define NUM_LAYERS 4
#define N_NODES 50000
#define N_PAD   50048            // 391 * 128
#define N_EDGES 800000
#define IN_FEAT 256
#define HIDDEN  512
#define MTILES  391

// ---------------- CSR scratch ----------------
__device__ int g_deg[N_NODES];
__device__ int g_row_ptr[N_NODES + 1];
__device__ int g_wptr[N_NODES];
__device__ int g_col[N_EDGES];

// ---------------- bf16 split operand buffers ----------------
__device__ __align__(16) __nv_bfloat16 g_xh[(size_t)N_PAD * IN_FEAT];
__device__ __align__(16) __nv_bfloat16 g_xl[(size_t)N_PAD * IN_FEAT];
__device__ __align__(16) __nv_bfloat16 g_agh[(size_t)NUM_LAYERS * N_PAD * HIDDEN];
__device__ __align__(16) __nv_bfloat16 g_agl[(size_t)NUM_LAYERS * N_PAD * HIDDEN];
__device__ __align__(16) __nv_bfloat16 g_o1h[(size_t)N_PAD * HIDDEN];
__device__ __align__(16) __nv_bfloat16 g_o1l[(size_t)N_PAD * HIDDEN];
__device__ __align__(16) __nv_bfloat16 g_o2h[(size_t)N_PAD * HIDDEN];
__device__ __align__(16) __nv_bfloat16 g_o2l[(size_t)N_PAD * HIDDEN];
#define W1_ELEMS (131072 + 3 * 262144)
#define W2_ELEMS (4 * 262144)
__device__ __align__(16) __nv_bfloat16 g_w1h[W1_ELEMS];
__device__ __align__(16) __nv_bfloat16 g_w1l[W1_ELEMS];
__device__ __align__(16) __nv_bfloat16 g_w2h[W2_ELEMS];
__device__ __align__(16) __nv_bfloat16 g_w2l[W2_ELEMS];

// ---------------- helpers ----------------
__device__ __forceinline__ uint32_t smem_u32(const void* p) {
    uint32_t a;
    asm("{ .reg .u64 t; cvta.to.shared.u64 t, %1; cvt.u32.u64 %0, t; }"
        : "=r"(a) : "l"(p));
    return a;
}

__device__ __forceinline__ void cpa16(uint32_t dst, const void* src) {
    asm volatile("cp.async.cg.shared.global [%0], [%1], 16;"
                 :: "r"(dst), "l"(src) : "memory");
}
#define CP_COMMIT() asm volatile("cp.async.commit_group;" ::: "memory")
#define CP_WAIT(n)  asm volatile("cp.async.wait_group %0;" :: "n"(n) : "memory")

#define LDSM4(r0, r1, r2, r3, addr)                                            \
    asm volatile("ldmatrix.sync.aligned.m8n8.x4.shared.b16 {%0,%1,%2,%3}, [%4];" \
                 : "=r"(r0), "=r"(r1), "=r"(r2), "=r"(r3) : "r"(addr))

#define MMA16816(c, a0, a1, a2, a3, b0, b1)                                    \
    asm volatile("mma.sync.aligned.m16n8k16.row.col.f32.bf16.bf16.f32 "        \
                 "{%0,%1,%2,%3},{%4,%5,%6,%7},{%8,%9},{%0,%1,%2,%3};"          \
                 : "+f"((c)[0]), "+f"((c)[1]), "+f"((c)[2]), "+f"((c)[3])      \
                 : "r"(a0), "r"(a1), "r"(a2), "r"(a3), "r"(b0), "r"(b1))

__device__ __forceinline__ void split_bf16(float v, __nv_bfloat16& h, __nv_bfloat16& l) {
    h = __float2bfloat16_rn(v);
    l = __float2bfloat16_rn(v - __bfloat162float(h));
}

// ================= CSR build =================
__global__ void k_zero_deg() {
    for (int i = blockIdx.x * blockDim.x + threadIdx.x; i < N_NODES;
         i += gridDim.x * blockDim.x)
        g_deg[i] = 0;
}

__global__ void k_hist(const int* __restrict__ ei) {
    int e = blockIdx.x * blockDim.x + threadIdx.x;
    if (e < N_EDGES) {
        int dst = ei[N_EDGES + e];
        if ((unsigned)dst < (unsigned)N_NODES) atomicAdd(&g_deg[dst], 1);
    }
}

__global__ void k_scan() {
    __shared__ int buf[1024];
    int t = threadIdx.x;
    int carry = 0;
    for (int base = 0; base < N_NODES; base += 1024) {
        int i = base + t;
        int v = (i < N_NODES) ? g_deg[i] : 0;
        buf[t] = v;
        __syncthreads();
#pragma unroll
        for (int off = 1; off < 1024; off <<= 1) {
            int tmp = (t >= off) ? buf[t - off] : 0;
            __syncthreads();
            buf[t] += tmp;
            __syncthreads();
        }
        int incl = buf[t];
        if (i < N_NODES) {
            g_row_ptr[i + 1] = carry + incl;
            g_wptr[i]        = carry + incl - v;
        }
        carry += buf[1023];
        __syncthreads();
    }
    if (t == 0) g_row_ptr[0] = 0;
}

__global__ void k_scatter(const int* __restrict__ ei) {
    int e = blockIdx.x * blockDim.x + threadIdx.x;
    if (e < N_EDGES) {
        int src = ei[e];
        int dst = ei[N_EDGES + e];
        if ((unsigned)dst < (unsigned)N_NODES && (unsigned)src < (unsigned)N_NODES) {
            int pos = atomicAdd(&g_wptr[dst], 1);
            g_col[pos] = src;
        }
    }
}

// ================= conversions =================
__global__ void k_convert_x(const float* __restrict__ x) {
    const int groups = N_PAD * IN_FEAT / 4;
    for (int g = blockIdx.x * blockDim.x + threadIdx.x; g < groups;
         g += gridDim.x * blockDim.x) {
        int e = g * 4;
        int m = e / IN_FEAT;
        float4 v = make_float4(0.f, 0.f, 0.f, 0.f);
        if (m < N_NODES) v = *(const float4*)&x[e];
        __nv_bfloat16 h0, h1, h2, h3, l0, l1, l2, l3;
        split_bf16(v.x, h0, l0); split_bf16(v.y, h1, l1);
        split_bf16(v.z, h2, l2); split_bf16(v.w, h3, l3);
        *(__nv_bfloat162*)&g_xh[e]     = __halves2bfloat162(h0, h1);
        *(__nv_bfloat162*)&g_xh[e + 2] = __halves2bfloat162(h2, h3);
        *(__nv_bfloat162*)&g_xl[e]     = __halves2bfloat162(l0, l1);
        *(__nv_bfloat162*)&g_xl[e + 2] = __halves2bfloat162(l2, l3);
    }
}

__global__ void k_convert_w(const float* __restrict__ Wi0,
                            const float* __restrict__ Wi_rest,
                            const float* __restrict__ Wr) {
    for (int g = blockIdx.x * blockDim.x + threadIdx.x; g < W1_ELEMS / 4;
         g += gridDim.x * blockDim.x) {
        int e = g * 4;
        float4 v = (e < 131072) ? *(const float4*)&Wi0[e]
                                : *(const float4*)&Wi_rest[e - 131072];
        __nv_bfloat16 h0, h1, h2, h3, l0, l1, l2, l3;
        split_bf16(v.x, h0, l0); split_bf16(v.y, h1, l1);
        split_bf16(v.z, h2, l2); split_bf16(v.w, h3, l3);
        *(__nv_bfloat162*)&g_w1h[e]     = __halves2bfloat162(h0, h1);
        *(__nv_bfloat162*)&g_w1h[e + 2] = __halves2bfloat162(h2, h3);
        *(__nv_bfloat162*)&g_w1l[e]     = __halves2bfloat162(l0, l1);
        *(__nv_bfloat162*)&g_w1l[e + 2] = __halves2bfloat162(l2, l3);
    }
    for (int g = blockIdx.x * blockDim.x + threadIdx.x; g < W2_ELEMS / 4;
         g += gridDim.x * blockDim.x) {
        int e = g * 4;
        float4 v = *(const float4*)&Wr[e];
        __nv_bfloat16 h0, h1, h2, h3, l0, l1, l2, l3;
        split_bf16(v.x, h0, l0); split_bf16(v.y, h1, l1);
        split_bf16(v.z, h2, l2); split_bf16(v.w, h3, l3);
        *(__nv_bfloat162*)&g_w2h[e]     = __halves2bfloat162(h0, h1);
        *(__nv_bfloat162*)&g_w2h[e + 2] = __halves2bfloat162(h2, h3);
        *(__nv_bfloat162*)&g_w2l[e]     = __halves2bfloat162(l0, l1);
        *(__nv_bfloat162*)&g_w2l[e + 2] = __halves2bfloat162(l2, l3);
    }
}

// ================= aggregation (one layer) -> bf16 hi/lo =================
__global__ void k_aggr(const float* __restrict__ states, int layer) {
    int node = blockIdx.x;      // 0..N_PAD-1
    int t    = threadIdx.x;     // 0..127, one float4 column each

    float4 acc = make_float4(0.f, 0.f, 0.f, 0.f);
    if (node < N_NODES) {
        const float4* S = (const float4*)(states + (size_t)layer * N_NODES * HIDDEN);
        int beg = g_row_ptr[node];
        int end = g_row_ptr[node + 1];
        for (int e = beg; e < end; e++) {
            int src = g_col[e];
            float4 v = S[(size_t)src * (HIDDEN / 4) + t];
            acc.x += v.x; acc.y += v.y; acc.z += v.z; acc.w += v.w;
        }
    }
    size_t o = ((size_t)layer * N_PAD + node) * HIDDEN + t * 4;
    __nv_bfloat16 h0, h1, h2, h3, l0, l1, l2, l3;
    split_bf16(acc.x, h0, l0); split_bf16(acc.y, h1, l1);
    split_bf16(acc.z, h2, l2); split_bf16(acc.w, h3, l3);
    *(__nv_bfloat162*)&g_agh[o]     = __halves2bfloat162(h0, h1);
    *(__nv_bfloat162*)&g_agh[o + 2] = __halves2bfloat162(h2, h3);
    *(__nv_bfloat162*)&g_agl[o]     = __halves2bfloat162(l0, l1);
    *(__nv_bfloat162*)&g_agl[o + 2] = __halves2bfloat162(l2, l3);
}

// ================= mma.sync dual-GEMM + tanh epilogue =================
// CTA tile 128(M) x 128(N) x 32(K); 8 warps in 2(M) x 4(N); warp tile 64x32.
// 2-stage cp.async double buffer => 81920 B SMEM => 2 CTAs/SM (proven config).
#define ROWP 40
#define TE   (128 * ROWP)              // elems per tile = 5120
#define STAGE_E (4 * TE)               // elems per stage = 20480
#define SMEM_BYTES (2 * STAGE_E * 2)   // 81920 B

__device__ __forceinline__ void load_stage(
    uint32_t sbase,
    const __nv_bfloat16* __restrict__ Ah, const __nv_bfloat16* __restrict__ Al,
    const __nv_bfloat16* __restrict__ Bh, const __nv_bfloat16* __restrict__ Bl,
    int bm, int n0, int kof, int astr, int bstr, int tid)
{
#pragma unroll
    for (int j = 0; j < 2; j++) {
        int idx = tid + j * 256;   // 0..511
        int r = idx >> 2;
        int c = idx & 3;
        uint32_t d = sbase + (uint32_t)(r * ROWP + c * 8) * 2;
        size_t ga = (size_t)(bm + r) * astr + kof + c * 8;
        size_t gb = (size_t)(n0 + r) * bstr + kof + c * 8;
        cpa16(d,              Ah + ga);
        cpa16(d + TE * 2,     Al + ga);
        cpa16(d + 2 * TE * 2, Bh + gb);
        cpa16(d + 3 * TE * 2, Bl + gb);
    }
}

__global__ __launch_bounds__(256)
void k_gemm_mma(int layer, int K1, int c1,
                const float* __restrict__ s_old,
                const float* __restrict__ leak,
                float* __restrict__ outp,
                int asel, int osel)
{
    extern __shared__ __nv_bfloat16 smem[];
    const uint32_t sm0 = smem_u32(smem);

    const int tid  = threadIdx.x;
    const int wid  = tid >> 5;
    const int lane = tid & 31;
    const int wm   = wid & 1;       // 0..1 (M)
    const int wn   = wid >> 1;      // 0..3 (N)
    const int bm   = blockIdx.y * 128;
    const int n0   = blockIdx.x * 128;

    // operand pointers from selectors
    const __nv_bfloat16 *a1h, *a1l;
    if (asel == 0)      { a1h = g_xh;  a1l = g_xl;  }
    else if (asel == 1) { a1h = g_o1h; a1l = g_o1l; }
    else                { a1h = g_o2h; a1l = g_o2l; }
    __nv_bfloat16 *oh = nullptr, *ol = nullptr;
    if (osel == 1)      { oh = g_o1h; ol = g_o1l; }
    else if (osel == 2) { oh = g_o2h; ol = g_o2l; }
    const __nv_bfloat16* a2h = g_agh + (size_t)layer * N_PAD * HIDDEN;
    const __nv_bfloat16* a2l = g_agl + (size_t)layer * N_PAD * HIDDEN;
    const size_t w1off = (layer == 0) ? 0 : (size_t)131072 + (size_t)(layer - 1) * 262144;
    const __nv_bfloat16* b1h = g_w1h + w1off;
    const __nv_bfloat16* b1l = g_w1l + w1off;
    const __nv_bfloat16* b2h = g_w2h + (size_t)layer * 262144;
    const __nv_bfloat16* b2l = g_w2l + (size_t)layer * 262144;

    float acc[4][4][4];
#pragma unroll
    for (int i = 0; i < 4; i++)
#pragma unroll
        for (int j = 0; j < 4; j++)
#pragma unroll
            for (int q = 0; q < 4; q++) acc[i][j][q] = 0.f;

    const int ctot = c1 + 16;

    // prologue: stage 0 = phase-1 chunk 0
    load_stage(sm0, a1h, a1l, b1h, b1l, bm, n0, 0, K1, K1, tid);
    CP_COMMIT();

    // ldmatrix lane-address components
    const int arow = (lane & 7) + ((lane >> 3) & 1) * 8;   // + wm*64 + mi*16
    const int acol = (lane >> 4) * 8;                       // + ks*16
    const int brow = (lane & 7) + (lane >> 4) * 8;          // + wn*32 + ng2*16
    const int bcol = ((lane >> 3) & 1) * 8;                 // + ks*16

    for (int ci = 0; ci < ctot; ci++) {
        if (ci + 1 < ctot) {
            int cj = ci + 1;
            uint32_t sb = sm0 + (uint32_t)((cj & 1) * STAGE_E) * 2;
            if (cj < c1)
                load_stage(sb, a1h, a1l, b1h, b1l, bm, n0, cj * 32, K1, K1, tid);
            else
                load_stage(sb, a2h, a2l, b2h, b2l, bm, n0, (cj - c1) * 32,
                           HIDDEN, HIDDEN, tid);
            CP_COMMIT();
            CP_WAIT(1);
        } else {
            CP_WAIT(0);
        }
        __syncthreads();

        const uint32_t sb = sm0 + (uint32_t)((ci & 1) * STAGE_E) * 2;
        const uint32_t aB = sb + (uint32_t)((wm * 64 + arow) * ROWP + acol) * 2;
        const uint32_t bB = sb + (uint32_t)(2 * TE + (wn * 32 + brow) * ROWP + bcol) * 2;

#pragma unroll
        for (int ks = 0; ks < 2; ks++) {
            uint32_t ah[4][4], al[4][4], bh[4][2], bl[4][2];
#pragma unroll
            for (int mi = 0; mi < 4; mi++) {
                uint32_t ad = aB + (uint32_t)(mi * 16 * ROWP + ks * 16) * 2;
                LDSM4(ah[mi][0], ah[mi][1], ah[mi][2], ah[mi][3], ad);
                LDSM4(al[mi][0], al[mi][1], al[mi][2], al[mi][3], ad + TE * 2);
            }
#pragma unroll
            for (int g2 = 0; g2 < 2; g2++) {
                uint32_t bd = bB + (uint32_t)(g2 * 16 * ROWP + ks * 16) * 2;
                uint32_t t0, t1, t2, t3;
                LDSM4(t0, t1, t2, t3, bd);
                bh[2 * g2][0] = t0; bh[2 * g2][1] = t1;
                bh[2 * g2 + 1][0] = t2; bh[2 * g2 + 1][1] = t3;
                LDSM4(t0, t1, t2, t3, bd + TE * 2);
                bl[2 * g2][0] = t0; bl[2 * g2][1] = t1;
                bl[2 * g2 + 1][0] = t2; bl[2 * g2 + 1][1] = t3;
            }
            // term-major issue order: all 16 accumulators are touched once per
            // term, so MMAs that share an accumulator are 16 issues apart
            // (>> HMMA latency) instead of back-to-back.
#pragma unroll
            for (int mi = 0; mi < 4; mi++)
#pragma unroll
                for (int ni = 0; ni < 4; ni++)
                    MMA16816(acc[mi][ni], ah[mi][0], ah[mi][1], ah[mi][2], ah[mi][3],
                             bh[ni][0], bh[ni][1]);
#pragma unroll
            for (int mi = 0; mi < 4; mi++)
#pragma unroll
                for (int ni = 0; ni < 4; ni++)
                    MMA16816(acc[mi][ni], ah[mi][0], ah[mi][1], ah[mi][2], ah[mi][3],
                             bl[ni][0], bl[ni][1]);
#pragma unroll
            for (int mi = 0; mi < 4; mi++)
#pragma unroll
                for (int ni = 0; ni < 4; ni++)
                    MMA16816(acc[mi][ni], al[mi][0], al[mi][1], al[mi][2], al[mi][3],
                             bh[ni][0], bh[ni][1]);
        }
        __syncthreads();
    }

    // ---------------- epilogue ----------------
    const float a   = leak[0];
    const float oma = 1.0f - a;
#pragma unroll
    for (int mi = 0; mi < 4; mi++) {
#pragma unroll
        for (int h = 0; h < 2; h++) {
            int mm = bm + wm * 64 + mi * 16 + (lane >> 2) + h * 8;
            bool valid = (mm < N_NODES);
            size_t rowb = (size_t)mm * HIDDEN + n0 + wn * 32 + (lane & 3) * 2;
#pragma unroll
            for (int ni = 0; ni < 4; ni++) {
                size_t off = rowb + ni * 8;
                if (valid) {
                    float c0 = acc[mi][ni][2 * h];
                    float c1 = acc[mi][ni][2 * h + 1];
                    float2 s = *(const float2*)&s_old[off];
                    float o0 = a * tanhf(c0) + oma * s.x;
                    float o1 = a * tanhf(c1) + oma * s.y;
                    *(float2*)&outp[off] = make_float2(o0, o1);
                    if (oh) {
                        __nv_bfloat16 h0, h1, l0, l1;
                        split_bf16(o0, h0, l0);
                        split_bf16(o1, h1, l1);
                        *(__nv_bfloat162*)&oh[off] = __halves2bfloat162(h0, h1);
                        *(__nv_bfloat162*)&ol[off] = __halves2bfloat162(l0, l1);
                    }
                } else if (oh) {
                    __nv_bfloat162 z =
                        __halves2bfloat162(__float2bfloat16_rn(0.f),
                                           __float2bfloat16_rn(0.f));
                    *(__nv_bfloat162*)&oh[off] = z;
                    *(__nv_bfloat162*)&ol[off] = z;
                }
            }
        }
    }
}

// ================= launch =================
extern "C" void kernel_launch(void* const* d_in, const int* in_sizes, int n_in,
                              void* d_out, int out_size)
{
    const int*   ei      = (const int*)d_in[0];       // [2, E] int32
    const float* x       = (const float*)d_in[1];     // [N, 256]
    const float* states  = (const float*)d_in[2];     // [4, N, 512]
    const float* Wi0     = (const float*)d_in[3];     // [512, 256]
    const float* Wi_rest = (const float*)d_in[4];     // [3, 512, 512]
    const float* Wr      = (const float*)d_in[5];     // [4, 512, 512]
    const float* leak    = (const float*)d_in[6];     // [1]
    float*       out     = (float*)d_out;             // [4, N, 512]

    (void)in_sizes; (void)n_in; (void)out_size;

    // one-time setup: smem carveout + side stream + events (host objects only;
    // no device memory is allocated)
    static cudaStream_t sAg = nullptr;
    static cudaEvent_t evFork = nullptr;
    static cudaEvent_t evA[NUM_LAYERS];
    if (sAg == nullptr) {
        cudaFuncSetAttribute(k_gemm_mma,
                             cudaFuncAttributeMaxDynamicSharedMemorySize,
                             SMEM_BYTES);
        cudaStreamCreateWithFlags(&sAg, cudaStreamNonBlocking);
        cudaEventCreateWithFlags(&evFork, cudaEventDisableTiming);
        for (int l = 0; l < NUM_LAYERS; l++)
            cudaEventCreateWithFlags(&evA[l], cudaEventDisableTiming);
    }

    // ---- fork the side stream FROM the capture-origin stream (stream 0) ----
    cudaEventRecord(evFork, 0);
    cudaStreamWaitEvent(sAg, evFork, 0);

    // ---- side stream: CSR build + 4 layer aggregations ----
    k_zero_deg<<<128, 256, 0, sAg>>>();
    k_hist<<<(N_EDGES + 255) / 256, 256, 0, sAg>>>(ei);
    k_scan<<<1, 1024, 0, sAg>>>();
    k_scatter<<<(N_EDGES + 255) / 256, 256, 0, sAg>>>(ei);
    for (int l = 0; l < NUM_LAYERS; l++) {
        k_aggr<<<N_PAD, 128, 0, sAg>>>(states, l);
        cudaEventRecord(evA[l], sAg);
    }

    // ---- main stream: conversions (overlap with CSR + aggregation) ----
    k_convert_x<<<4096, 256>>>(x);
    k_convert_w<<<1024, 256>>>(Wi0, Wi_rest, Wr);

    // ---- main stream: sequential GEMM chain; GEMM l waits on aggr l ----
    dim3 grid(HIDDEN / 128, MTILES);
    const int asel[4] = {0, 1, 2, 1};
    const int osel[4] = {1, 2, 1, 0};
    for (int l = 0; l < NUM_LAYERS; l++) {
        int K1 = (l == 0) ? IN_FEAT : HIDDEN;
        int c1 = K1 / 32;
        const float* so = states + (size_t)l * N_NODES * HIDDEN;
        float*       ol = out + (size_t)l * N_NODES * HIDDEN;
        cudaStreamWaitEvent(0, evA[l], 0);
        k_gemm_mma<<<grid, 256, SMEM_BYTES>>>(l, K1, c1, so, leak, ol,
                                              asel[l], osel[l]);
    }
}

// round 9
// speedup vs baseline: 1.2120x; 1.0217x over previous
#include <cuda_runtime.h>
#include <cuda_bf16.h>
#include <math.h>
#include <stdint.h>

#define NUM_LAYERS 4
#define N_NODES 50000
#define N_PAD   50048            // 391 * 128 = 1564 * 32
#define N_EDGES 800000
#define IN_FEAT 256
#define HIDDEN  512
#define MTILES  391
#define NGEMM_BLKS 1564          // 4 * 391
#define NAGGR_BLKS 1564          // N_PAD / 32

// ---------------- CSR scratch ----------------
__device__ int g_deg[N_NODES];
__device__ int g_row_ptr[N_NODES + 1];
__device__ int g_wptr[N_NODES];
__device__ int g_col[N_EDGES];

// ---------------- bf16 split operand buffers ----------------
__device__ __align__(16) __nv_bfloat16 g_xh[(size_t)N_PAD * IN_FEAT];
__device__ __align__(16) __nv_bfloat16 g_xl[(size_t)N_PAD * IN_FEAT];
__device__ __align__(16) __nv_bfloat16 g_agh[(size_t)NUM_LAYERS * N_PAD * HIDDEN];
__device__ __align__(16) __nv_bfloat16 g_agl[(size_t)NUM_LAYERS * N_PAD * HIDDEN];
__device__ __align__(16) __nv_bfloat16 g_o1h[(size_t)N_PAD * HIDDEN];
__device__ __align__(16) __nv_bfloat16 g_o1l[(size_t)N_PAD * HIDDEN];
__device__ __align__(16) __nv_bfloat16 g_o2h[(size_t)N_PAD * HIDDEN];
__device__ __align__(16) __nv_bfloat16 g_o2l[(size_t)N_PAD * HIDDEN];
#define W1_ELEMS (131072 + 3 * 262144)
#define W2_ELEMS (4 * 262144)
__device__ __align__(16) __nv_bfloat16 g_w1h[W1_ELEMS];
__device__ __align__(16) __nv_bfloat16 g_w1l[W1_ELEMS];
__device__ __align__(16) __nv_bfloat16 g_w2h[W2_ELEMS];
__device__ __align__(16) __nv_bfloat16 g_w2l[W2_ELEMS];

// ---------------- helpers ----------------
__device__ __forceinline__ uint32_t smem_u32(const void* p) {
    uint32_t a;
    asm("{ .reg .u64 t; cvta.to.shared.u64 t, %1; cvt.u32.u64 %0, t; }"
        : "=r"(a) : "l"(p));
    return a;
}

__device__ __forceinline__ void cpa16(uint32_t dst, const void* src) {
    asm volatile("cp.async.cg.shared.global [%0], [%1], 16;"
                 :: "r"(dst), "l"(src) : "memory");
}
#define CP_COMMIT() asm volatile("cp.async.commit_group;" ::: "memory")
#define CP_WAIT(n)  asm volatile("cp.async.wait_group %0;" :: "n"(n) : "memory")

#define LDSM4(r0, r1, r2, r3, addr)                                            \
    asm volatile("ldmatrix.sync.aligned.m8n8.x4.shared.b16 {%0,%1,%2,%3}, [%4];" \
                 : "=r"(r0), "=r"(r1), "=r"(r2), "=r"(r3) : "r"(addr))

#define MMA16816(c, a0, a1, a2, a3, b0, b1)                                    \
    asm volatile("mma.sync.aligned.m16n8k16.row.col.f32.bf16.bf16.f32 "        \
                 "{%0,%1,%2,%3},{%4,%5,%6,%7},{%8,%9},{%0,%1,%2,%3};"          \
                 : "+f"((c)[0]), "+f"((c)[1]), "+f"((c)[2]), "+f"((c)[3])      \
                 : "r"(a0), "r"(a1), "r"(a2), "r"(a3), "r"(b0), "r"(b1))

__device__ __forceinline__ void split_bf16(float v, __nv_bfloat16& h, __nv_bfloat16& l) {
    h = __float2bfloat16_rn(v);
    l = __float2bfloat16_rn(v - __bfloat162float(h));
}

// fast tanh: 1 - 2/(e^{2x}+1); abs err ~1e-7, handles +-inf saturation
__device__ __forceinline__ float fast_tanh(float x) {
    float t = __expf(2.0f * x);
    return 1.0f - __fdividef(2.0f, t + 1.0f);
}

// ================= CSR build =================
__global__ void k_zero_deg() {
    for (int i = blockIdx.x * blockDim.x + threadIdx.x; i < N_NODES;
         i += gridDim.x * blockDim.x)
        g_deg[i] = 0;
}

__global__ void k_hist(const int* __restrict__ ei) {
    int e = blockIdx.x * blockDim.x + threadIdx.x;
    if (e < N_EDGES) {
        int dst = ei[N_EDGES + e];
        if ((unsigned)dst < (unsigned)N_NODES) atomicAdd(&g_deg[dst], 1);
    }
}

__global__ void k_scan() {
    __shared__ int buf[1024];
    int t = threadIdx.x;
    int carry = 0;
    for (int base = 0; base < N_NODES; base += 1024) {
        int i = base + t;
        int v = (i < N_NODES) ? g_deg[i] : 0;
        buf[t] = v;
        __syncthreads();
#pragma unroll
        for (int off = 1; off < 1024; off <<= 1) {
            int tmp = (t >= off) ? buf[t - off] : 0;
            __syncthreads();
            buf[t] += tmp;
            __syncthreads();
        }
        int incl = buf[t];
        if (i < N_NODES) {
            g_row_ptr[i + 1] = carry + incl;
            g_wptr[i]        = carry + incl - v;
        }
        carry += buf[1023];
        __syncthreads();
    }
    if (t == 0) g_row_ptr[0] = 0;
}

__global__ void k_scatter(const int* __restrict__ ei) {
    int e = blockIdx.x * blockDim.x + threadIdx.x;
    if (e < N_EDGES) {
        int src = ei[e];
        int dst = ei[N_EDGES + e];
        if ((unsigned)dst < (unsigned)N_NODES && (unsigned)src < (unsigned)N_NODES) {
            int pos = atomicAdd(&g_wptr[dst], 1);
            g_col[pos] = src;
        }
    }
}

// ================= conversions =================
__global__ void k_convert_x(const float* __restrict__ x) {
    const int groups = N_PAD * IN_FEAT / 4;
    for (int g = blockIdx.x * blockDim.x + threadIdx.x; g < groups;
         g += gridDim.x * blockDim.x) {
        int e = g * 4;
        int m = e / IN_FEAT;
        float4 v = make_float4(0.f, 0.f, 0.f, 0.f);
        if (m < N_NODES) v = *(const float4*)&x[e];
        __nv_bfloat16 h0, h1, h2, h3, l0, l1, l2, l3;
        split_bf16(v.x, h0, l0); split_bf16(v.y, h1, l1);
        split_bf16(v.z, h2, l2); split_bf16(v.w, h3, l3);
        *(__nv_bfloat162*)&g_xh[e]     = __halves2bfloat162(h0, h1);
        *(__nv_bfloat162*)&g_xh[e + 2] = __halves2bfloat162(h2, h3);
        *(__nv_bfloat162*)&g_xl[e]     = __halves2bfloat162(l0, l1);
        *(__nv_bfloat162*)&g_xl[e + 2] = __halves2bfloat162(l2, l3);
    }
}

__global__ void k_convert_w(const float* __restrict__ Wi0,
                            const float* __restrict__ Wi_rest,
                            const float* __restrict__ Wr) {
    for (int g = blockIdx.x * blockDim.x + threadIdx.x; g < W1_ELEMS / 4;
         g += gridDim.x * blockDim.x) {
        int e = g * 4;
        float4 v = (e < 131072) ? *(const float4*)&Wi0[e]
                                : *(const float4*)&Wi_rest[e - 131072];
        __nv_bfloat16 h0, h1, h2, h3, l0, l1, l2, l3;
        split_bf16(v.x, h0, l0); split_bf16(v.y, h1, l1);
        split_bf16(v.z, h2, l2); split_bf16(v.w, h3, l3);
        *(__nv_bfloat162*)&g_w1h[e]     = __halves2bfloat162(h0, h1);
        *(__nv_bfloat162*)&g_w1h[e + 2] = __halves2bfloat162(h2, h3);
        *(__nv_bfloat162*)&g_w1l[e]     = __halves2bfloat162(l0, l1);
        *(__nv_bfloat162*)&g_w1l[e + 2] = __halves2bfloat162(l2, l3);
    }
    for (int g = blockIdx.x * blockDim.x + threadIdx.x; g < W2_ELEMS / 4;
         g += gridDim.x * blockDim.x) {
        int e = g * 4;
        float4 v = *(const float4*)&Wr[e];
        __nv_bfloat16 h0, h1, h2, h3, l0, l1, l2, l3;
        split_bf16(v.x, h0, l0); split_bf16(v.y, h1, l1);
        split_bf16(v.z, h2, l2); split_bf16(v.w, h3, l3);
        *(__nv_bfloat162*)&g_w2h[e]     = __halves2bfloat162(h0, h1);
        *(__nv_bfloat162*)&g_w2h[e + 2] = __halves2bfloat162(h2, h3);
        *(__nv_bfloat162*)&g_w2l[e]     = __halves2bfloat162(l0, l1);
        *(__nv_bfloat162*)&g_w2l[e + 2] = __halves2bfloat162(l2, l3);
    }
}

// ================= aggregation core (32 nodes per 256-thread CTA) =========
// states_layer points at the [N_NODES, 512] fp32 state slab for ONE layer.
// Output goes to g_agh/g_agl at layer index lout.
__device__ __forceinline__ void aggr_block(int aid, int lout,
                                           const float* __restrict__ states_layer)
{
    const int warp = threadIdx.x >> 5;
    const int lane = threadIdx.x & 31;
    const float4* S = (const float4*)states_layer;   // 128 float4 per row

#pragma unroll 1
    for (int i = 0; i < 4; i++) {
        int node = aid * 32 + warp + 8 * i;          // < N_PAD by construction
        float4 acc0 = make_float4(0.f, 0.f, 0.f, 0.f);
        float4 acc1 = acc0, acc2 = acc0, acc3 = acc0;
        if (node < N_NODES) {
            int beg = g_row_ptr[node];
            int end = g_row_ptr[node + 1];
            for (int e = beg; e < end; e++) {
                int src = g_col[e];
                const float4* row = S + (size_t)src * (HIDDEN / 4);
                float4 v0 = row[lane];
                float4 v1 = row[lane + 32];
                float4 v2 = row[lane + 64];
                float4 v3 = row[lane + 96];
                acc0.x += v0.x; acc0.y += v0.y; acc0.z += v0.z; acc0.w += v0.w;
                acc1.x += v1.x; acc1.y += v1.y; acc1.z += v1.z; acc1.w += v1.w;
                acc2.x += v2.x; acc2.y += v2.y; acc2.z += v2.z; acc2.w += v2.w;
                acc3.x += v3.x; acc3.y += v3.y; acc3.z += v3.z; acc3.w += v3.w;
            }
        }
        size_t base = ((size_t)lout * N_PAD + node) * HIDDEN;
        float4 accs[4] = {acc0, acc1, acc2, acc3};
#pragma unroll
        for (int k = 0; k < 4; k++) {
            size_t o = base + (size_t)(lane + 32 * k) * 4;
            __nv_bfloat16 h0, h1, h2, h3, l0, l1, l2, l3;
            split_bf16(accs[k].x, h0, l0); split_bf16(accs[k].y, h1, l1);
            split_bf16(accs[k].z, h2, l2); split_bf16(accs[k].w, h3, l3);
            *(__nv_bfloat162*)&g_agh[o]     = __halves2bfloat162(h0, h1);
            *(__nv_bfloat162*)&g_agh[o + 2] = __halves2bfloat162(h2, h3);
            *(__nv_bfloat162*)&g_agl[o]     = __halves2bfloat162(l0, l1);
            *(__nv_bfloat162*)&g_agl[o + 2] = __halves2bfloat162(l2, l3);
        }
    }
}

// standalone aggregation kernel (layer 0 bootstrap)
__global__ void k_aggr0(const float* __restrict__ states) {
    aggr_block(blockIdx.x, 0, states);
}

// ================= fused mma.sync dual-GEMM + tanh epilogue + next-layer aggr
// GEMM CTA tile 128x128x32; 8 warps 2(M)x4(N); warp tile 64x32.
// 2-stage cp.async double buffer => 81920 B SMEM => 2 CTAs/SM.
// When do_aggr=1, odd blockIdx.x CTAs compute aggr for layer+1 instead.
#define ROWP 40
#define TE   (128 * ROWP)              // elems per tile = 5120
#define STAGE_E (4 * TE)               // elems per stage = 20480
#define SMEM_BYTES (2 * STAGE_E * 2)   // 81920 B

__device__ __forceinline__ void load_stage(
    uint32_t sbase,
    const __nv_bfloat16* __restrict__ Ah, const __nv_bfloat16* __restrict__ Al,
    const __nv_bfloat16* __restrict__ Bh, const __nv_bfloat16* __restrict__ Bl,
    int bm, int n0, int kof, int astr, int bstr, int tid)
{
#pragma unroll
    for (int j = 0; j < 2; j++) {
        int idx = tid + j * 256;   // 0..511
        int r = idx >> 2;
        int c = idx & 3;
        uint32_t d = sbase + (uint32_t)(r * ROWP + c * 8) * 2;
        size_t ga = (size_t)(bm + r) * astr + kof + c * 8;
        size_t gb = (size_t)(n0 + r) * bstr + kof + c * 8;
        cpa16(d,              Ah + ga);
        cpa16(d + TE * 2,     Al + ga);
        cpa16(d + 2 * TE * 2, Bh + gb);
        cpa16(d + 3 * TE * 2, Bl + gb);
    }
}

__global__ __launch_bounds__(256)
void k_gemm_mma(int layer, int K1, int c1,
                const float* __restrict__ s_old,
                const float* __restrict__ leak,
                float* __restrict__ outp,
                int asel, int osel,
                int do_aggr,
                const float* __restrict__ states_next)
{
    // ---- block-type decode (block-uniform branch) ----
    if (do_aggr && (blockIdx.x & 1)) {
        aggr_block(blockIdx.x >> 1, layer + 1, states_next);
        return;
    }
    const int gid = do_aggr ? (blockIdx.x >> 1) : blockIdx.x;   // 0..1563

    extern __shared__ __nv_bfloat16 smem[];
    const uint32_t sm0 = smem_u32(smem);

    const int tid  = threadIdx.x;
    const int wid  = tid >> 5;
    const int lane = tid & 31;
    const int wm   = wid & 1;       // 0..1 (M)
    const int wn   = wid >> 1;      // 0..3 (N)
    const int bm   = (gid >> 2) * 128;
    const int n0   = (gid & 3) * 128;

    // operand pointers from selectors
    const __nv_bfloat16 *a1h, *a1l;
    if (asel == 0)      { a1h = g_xh;  a1l = g_xl;  }
    else if (asel == 1) { a1h = g_o1h; a1l = g_o1l; }
    else                { a1h = g_o2h; a1l = g_o2l; }
    __nv_bfloat16 *oh = nullptr, *ol = nullptr;
    if (osel == 1)      { oh = g_o1h; ol = g_o1l; }
    else if (osel == 2) { oh = g_o2h; ol = g_o2l; }
    const __nv_bfloat16* a2h = g_agh + (size_t)layer * N_PAD * HIDDEN;
    const __nv_bfloat16* a2l = g_agl + (size_t)layer * N_PAD * HIDDEN;
    const size_t w1off = (layer == 0) ? 0 : (size_t)131072 + (size_t)(layer - 1) * 262144;
    const __nv_bfloat16* b1h = g_w1h + w1off;
    const __nv_bfloat16* b1l = g_w1l + w1off;
    const __nv_bfloat16* b2h = g_w2h + (size_t)layer * 262144;
    const __nv_bfloat16* b2l = g_w2l + (size_t)layer * 262144;

    float acc[4][4][4];
#pragma unroll
    for (int i = 0; i < 4; i++)
#pragma unroll
        for (int j = 0; j < 4; j++)
#pragma unroll
            for (int q = 0; q < 4; q++) acc[i][j][q] = 0.f;

    const int ctot = c1 + 16;

    // prologue: stage 0 = phase-1 chunk 0
    load_stage(sm0, a1h, a1l, b1h, b1l, bm, n0, 0, K1, K1, tid);
    CP_COMMIT();

    // ldmatrix lane-address components
    const int arow = (lane & 7) + ((lane >> 3) & 1) * 8;   // + wm*64 + mi*16
    const int acol = (lane >> 4) * 8;                       // + ks*16
    const int brow = (lane & 7) + (lane >> 4) * 8;          // + wn*32 + ng2*16
    const int bcol = ((lane >> 3) & 1) * 8;                 // + ks*16

    for (int ci = 0; ci < ctot; ci++) {
        if (ci + 1 < ctot) {
            int cj = ci + 1;
            uint32_t sb = sm0 + (uint32_t)((cj & 1) * STAGE_E) * 2;
            if (cj < c1)
                load_stage(sb, a1h, a1l, b1h, b1l, bm, n0, cj * 32, K1, K1, tid);
            else
                load_stage(sb, a2h, a2l, b2h, b2l, bm, n0, (cj - c1) * 32,
                           HIDDEN, HIDDEN, tid);
            CP_COMMIT();
            CP_WAIT(1);
        } else {
            CP_WAIT(0);
        }
        __syncthreads();

        const uint32_t sb = sm0 + (uint32_t)((ci & 1) * STAGE_E) * 2;
        const uint32_t aB = sb + (uint32_t)((wm * 64 + arow) * ROWP + acol) * 2;
        const uint32_t bB = sb + (uint32_t)(2 * TE + (wn * 32 + brow) * ROWP + bcol) * 2;

#pragma unroll
        for (int ks = 0; ks < 2; ks++) {
            uint32_t ah[4][4], al[4][4], bh[4][2], bl[4][2];
#pragma unroll
            for (int mi = 0; mi < 4; mi++) {
                uint32_t ad = aB + (uint32_t)(mi * 16 * ROWP + ks * 16) * 2;
                LDSM4(ah[mi][0], ah[mi][1], ah[mi][2], ah[mi][3], ad);
                LDSM4(al[mi][0], al[mi][1], al[mi][2], al[mi][3], ad + TE * 2);
            }
#pragma unroll
            for (int g2 = 0; g2 < 2; g2++) {
                uint32_t bd = bB + (uint32_t)(g2 * 16 * ROWP + ks * 16) * 2;
                uint32_t t0, t1, t2, t3;
                LDSM4(t0, t1, t2, t3, bd);
                bh[2 * g2][0] = t0; bh[2 * g2][1] = t1;
                bh[2 * g2 + 1][0] = t2; bh[2 * g2 + 1][1] = t3;
                LDSM4(t0, t1, t2, t3, bd + TE * 2);
                bl[2 * g2][0] = t0; bl[2 * g2][1] = t1;
                bl[2 * g2 + 1][0] = t2; bl[2 * g2 + 1][1] = t3;
            }
#pragma unroll
            for (int mi = 0; mi < 4; mi++)
#pragma unroll
                for (int ni = 0; ni < 4; ni++)
                    MMA16816(acc[mi][ni], ah[mi][0], ah[mi][1], ah[mi][2], ah[mi][3],
                             bh[ni][0], bh[ni][1]);
#pragma unroll
            for (int mi = 0; mi < 4; mi++)
#pragma unroll
                for (int ni = 0; ni < 4; ni++)
                    MMA16816(acc[mi][ni], ah[mi][0], ah[mi][1], ah[mi][2], ah[mi][3],
                             bl[ni][0], bl[ni][1]);
#pragma unroll
            for (int mi = 0; mi < 4; mi++)
#pragma unroll
                for (int ni = 0; ni < 4; ni++)
                    MMA16816(acc[mi][ni], al[mi][0], al[mi][1], al[mi][2], al[mi][3],
                             bh[ni][0], bh[ni][1]);
        }
        __syncthreads();
    }

    // ---------------- epilogue ----------------
    const float a   = leak[0];
    const float oma = 1.0f - a;
#pragma unroll
    for (int mi = 0; mi < 4; mi++) {
#pragma unroll
        for (int h = 0; h < 2; h++) {
            int mm = bm + wm * 64 + mi * 16 + (lane >> 2) + h * 8;
            bool valid = (mm < N_NODES);
            size_t rowb = (size_t)mm * HIDDEN + n0 + wn * 32 + (lane & 3) * 2;
#pragma unroll
            for (int ni = 0; ni < 4; ni++) {
                size_t off = rowb + ni * 8;
                if (valid) {
                    float c0 = acc[mi][ni][2 * h];
                    float c1 = acc[mi][ni][2 * h + 1];
                    float2 s = *(const float2*)&s_old[off];
                    float o0 = a * fast_tanh(c0) + oma * s.x;
                    float o1 = a * fast_tanh(c1) + oma * s.y;
                    *(float2*)&outp[off] = make_float2(o0, o1);
                    if (oh) {
                        __nv_bfloat16 h0, h1, l0, l1;
                        split_bf16(o0, h0, l0);
                        split_bf16(o1, h1, l1);
                        *(__nv_bfloat162*)&oh[off] = __halves2bfloat162(h0, h1);
                        *(__nv_bfloat162*)&ol[off] = __halves2bfloat162(l0, l1);
                    }
                } else if (oh) {
                    __nv_bfloat162 z =
                        __halves2bfloat162(__float2bfloat16_rn(0.f),
                                           __float2bfloat16_rn(0.f));
                    *(__nv_bfloat162*)&oh[off] = z;
                    *(__nv_bfloat162*)&ol[off] = z;
                }
            }
        }
    }
}

// ================= launch =================
extern "C" void kernel_launch(void* const* d_in, const int* in_sizes, int n_in,
                              void* d_out, int out_size)
{
    const int*   ei      = (const int*)d_in[0];       // [2, E] int32
    const float* x       = (const float*)d_in[1];     // [N, 256]
    const float* states  = (const float*)d_in[2];     // [4, N, 512]
    const float* Wi0     = (const float*)d_in[3];     // [512, 256]
    const float* Wi_rest = (const float*)d_in[4];     // [3, 512, 512]
    const float* Wr      = (const float*)d_in[5];     // [4, 512, 512]
    const float* leak    = (const float*)d_in[6];     // [1]
    float*       out     = (float*)d_out;             // [4, N, 512]

    (void)in_sizes; (void)n_in; (void)out_size;

    static int init_done = 0;
    if (!init_done) {
        cudaFuncSetAttribute(k_gemm_mma,
                             cudaFuncAttributeMaxDynamicSharedMemorySize,
                             SMEM_BYTES);
        init_done = 1;
    }

    // CSR build
    k_zero_deg<<<128, 256>>>();
    k_hist<<<(N_EDGES + 255) / 256, 256>>>(ei);
    k_scan<<<1, 1024>>>();
    k_scatter<<<(N_EDGES + 255) / 256, 256>>>(ei);

    // operand conversion
    k_convert_x<<<4096, 256>>>(x);
    k_convert_w<<<1024, 256>>>(Wi0, Wi_rest, Wr);

    // layer-0 aggregation (bootstrap; layers 1-3 fused into the GEMMs)
    k_aggr0<<<NAGGR_BLKS, 256>>>(states);

    // sequential fused GEMM chain; GEMM l also computes aggr[l+1]
    const int asel[4] = {0, 1, 2, 1};
    const int osel[4] = {1, 2, 1, 0};
    for (int l = 0; l < NUM_LAYERS; l++) {
        int K1 = (l == 0) ? IN_FEAT : HIDDEN;
        int c1 = K1 / 32;
        int do_aggr = (l < NUM_LAYERS - 1) ? 1 : 0;
        int nblk = do_aggr ? (NGEMM_BLKS + NAGGR_BLKS) : NGEMM_BLKS;
        const float* so = states + (size_t)l * N_NODES * HIDDEN;
        const float* sn = states + (size_t)(do_aggr ? (l + 1) : l) * N_NODES * HIDDEN;
        float*       ol = out + (size_t)l * N_NODES * HIDDEN;
        k_gemm_mma<<<nblk, 256, SMEM_BYTES>>>(l, K1, c1, so, leak, ol,
                                              asel[l], osel[l], do_aggr, sn);
    }
}

// round 11
// speedup vs baseline: 1.2164x; 1.0036x over previous
#include <cuda_runtime.h>
#include <cuda_bf16.h>
#include <math.h>
#include <stdint.h>

#define NUM_LAYERS 4
#define N_NODES 50000
#define N_PAD   50048            // 391 * 128
#define N_EDGES 800000
#define IN_FEAT 256
#define HIDDEN  512
#define MTILES  391
#define NGEMM_BLKS 1564          // 4 * 391

// ---------------- CSR scratch ----------------
__device__ int g_deg[N_NODES];
__device__ int g_row_ptr[N_NODES + 1];
__device__ int g_wptr[N_NODES];
__device__ int g_col[N_EDGES];

// ---------------- bf16 split operand buffers ----------------
__device__ __align__(16) __nv_bfloat16 g_xh[(size_t)N_PAD * IN_FEAT];
__device__ __align__(16) __nv_bfloat16 g_xl[(size_t)N_PAD * IN_FEAT];
__device__ __align__(16) __nv_bfloat16 g_agh[(size_t)NUM_LAYERS * N_PAD * HIDDEN];
__device__ __align__(16) __nv_bfloat16 g_agl[(size_t)NUM_LAYERS * N_PAD * HIDDEN];
__device__ __align__(16) __nv_bfloat16 g_o1h[(size_t)N_PAD * HIDDEN];
__device__ __align__(16) __nv_bfloat16 g_o1l[(size_t)N_PAD * HIDDEN];
__device__ __align__(16) __nv_bfloat16 g_o2h[(size_t)N_PAD * HIDDEN];
__device__ __align__(16) __nv_bfloat16 g_o2l[(size_t)N_PAD * HIDDEN];
#define W1_ELEMS (131072 + 3 * 262144)
#define W2_ELEMS (4 * 262144)
__device__ __align__(16) __nv_bfloat16 g_w1h[W1_ELEMS];
__device__ __align__(16) __nv_bfloat16 g_w1l[W1_ELEMS];
__device__ __align__(16) __nv_bfloat16 g_w2h[W2_ELEMS];
__device__ __align__(16) __nv_bfloat16 g_w2l[W2_ELEMS];

// ---------------- helpers ----------------
__device__ __forceinline__ uint32_t smem_u32(const void* p) {
    uint32_t a;
    asm("{ .reg .u64 t; cvta.to.shared.u64 t, %1; cvt.u32.u64 %0, t; }"
        : "=r"(a) : "l"(p));
    return a;
}

__device__ __forceinline__ void cpa16(uint32_t dst, const void* src) {
    asm volatile("cp.async.cg.shared.global [%0], [%1], 16;"
                 :: "r"(dst), "l"(src) : "memory");
}
#define CP_COMMIT() asm volatile("cp.async.commit_group;" ::: "memory")
#define CP_WAIT(n)  asm volatile("cp.async.wait_group %0;" :: "n"(n) : "memory")

#define LDSM4(r0, r1, r2, r3, addr)                                            \
    asm volatile("ldmatrix.sync.aligned.m8n8.x4.shared.b16 {%0,%1,%2,%3}, [%4];" \
                 : "=r"(r0), "=r"(r1), "=r"(r2), "=r"(r3) : "r"(addr))

#define MMA16816(c, a0, a1, a2, a3, b0, b1)                                    \
    asm volatile("mma.sync.aligned.m16n8k16.row.col.f32.bf16.bf16.f32 "        \
                 "{%0,%1,%2,%3},{%4,%5,%6,%7},{%8,%9},{%0,%1,%2,%3};"          \
                 : "+f"((c)[0]), "+f"((c)[1]), "+f"((c)[2]), "+f"((c)[3])      \
                 : "r"(a0), "r"(a1), "r"(a2), "r"(a3), "r"(b0), "r"(b1))

__device__ __forceinline__ void split_bf16(float v, __nv_bfloat16& h, __nv_bfloat16& l) {
    h = __float2bfloat16_rn(v);
    l = __float2bfloat16_rn(v - __bfloat162float(h));
}

// fast tanh: 1 - 2/(e^{2x}+1); abs err ~1e-7
__device__ __forceinline__ float fast_tanh(float x) {
    float t = __expf(2.0f * x);
    return 1.0f - __fdividef(2.0f, t + 1.0f);
}

// ================= CSR build =================
__global__ void k_zero_deg() {
    for (int i = blockIdx.x * blockDim.x + threadIdx.x; i < N_NODES;
         i += gridDim.x * blockDim.x)
        g_deg[i] = 0;
}

__global__ void k_hist(const int* __restrict__ ei) {
    int e = blockIdx.x * blockDim.x + threadIdx.x;
    if (e < N_EDGES) {
        int dst = ei[N_EDGES + e];
        if ((unsigned)dst < (unsigned)N_NODES) atomicAdd(&g_deg[dst], 1);
    }
}

__global__ void k_scan() {
    __shared__ int buf[1024];
    int t = threadIdx.x;
    int carry = 0;
    for (int base = 0; base < N_NODES; base += 1024) {
        int i = base + t;
        int v = (i < N_NODES) ? g_deg[i] : 0;
        buf[t] = v;
        __syncthreads();
#pragma unroll
        for (int off = 1; off < 1024; off <<= 1) {
            int tmp = (t >= off) ? buf[t - off] : 0;
            __syncthreads();
            buf[t] += tmp;
            __syncthreads();
        }
        int incl = buf[t];
        if (i < N_NODES) {
            g_row_ptr[i + 1] = carry + incl;
            g_wptr[i]        = carry + incl - v;
        }
        carry += buf[1023];
        __syncthreads();
    }
    if (t == 0) g_row_ptr[0] = 0;
}

__global__ void k_scatter(const int* __restrict__ ei) {
    int e = blockIdx.x * blockDim.x + threadIdx.x;
    if (e < N_EDGES) {
        int src = ei[e];
        int dst = ei[N_EDGES + e];
        if ((unsigned)dst < (unsigned)N_NODES && (unsigned)src < (unsigned)N_NODES) {
            int pos = atomicAdd(&g_wptr[dst], 1);
            g_col[pos] = src;
        }
    }
}

// ================= conversions =================
__global__ void k_convert_x(const float* __restrict__ x) {
    const int groups = N_PAD * IN_FEAT / 4;
    for (int g = blockIdx.x * blockDim.x + threadIdx.x; g < groups;
         g += gridDim.x * blockDim.x) {
        int e = g * 4;
        int m = e / IN_FEAT;
        float4 v = make_float4(0.f, 0.f, 0.f, 0.f);
        if (m < N_NODES) v = *(const float4*)&x[e];
        __nv_bfloat16 h0, h1, h2, h3, l0, l1, l2, l3;
        split_bf16(v.x, h0, l0); split_bf16(v.y, h1, l1);
        split_bf16(v.z, h2, l2); split_bf16(v.w, h3, l3);
        *(__nv_bfloat162*)&g_xh[e]     = __halves2bfloat162(h0, h1);
        *(__nv_bfloat162*)&g_xh[e + 2] = __halves2bfloat162(h2, h3);
        *(__nv_bfloat162*)&g_xl[e]     = __halves2bfloat162(l0, l1);
        *(__nv_bfloat162*)&g_xl[e + 2] = __halves2bfloat162(l2, l3);
    }
}

__global__ void k_convert_w(const float* __restrict__ Wi0,
                            const float* __restrict__ Wi_rest,
                            const float* __restrict__ Wr) {
    for (int g = blockIdx.x * blockDim.x + threadIdx.x; g < W1_ELEMS / 4;
         g += gridDim.x * blockDim.x) {
        int e = g * 4;
        float4 v = (e < 131072) ? *(const float4*)&Wi0[e]
                                : *(const float4*)&Wi_rest[e - 131072];
        __nv_bfloat16 h0, h1, h2, h3, l0, l1, l2, l3;
        split_bf16(v.x, h0, l0); split_bf16(v.y, h1, l1);
        split_bf16(v.z, h2, l2); split_bf16(v.w, h3, l3);
        *(__nv_bfloat162*)&g_w1h[e]     = __halves2bfloat162(h0, h1);
        *(__nv_bfloat162*)&g_w1h[e + 2] = __halves2bfloat162(h2, h3);
        *(__nv_bfloat162*)&g_w1l[e]     = __halves2bfloat162(l0, l1);
        *(__nv_bfloat162*)&g_w1l[e + 2] = __halves2bfloat162(l2, l3);
    }
    for (int g = blockIdx.x * blockDim.x + threadIdx.x; g < W2_ELEMS / 4;
         g += gridDim.x * blockDim.x) {
        int e = g * 4;
        float4 v = *(const float4*)&Wr[e];
        __nv_bfloat16 h0, h1, h2, h3, l0, l1, l2, l3;
        split_bf16(v.x, h0, l0); split_bf16(v.y, h1, l1);
        split_bf16(v.z, h2, l2); split_bf16(v.w, h3, l3);
        *(__nv_bfloat162*)&g_w2h[e]     = __halves2bfloat162(h0, h1);
        *(__nv_bfloat162*)&g_w2h[e + 2] = __halves2bfloat162(h2, h3);
        *(__nv_bfloat162*)&g_w2l[e]     = __halves2bfloat162(l0, l1);
        *(__nv_bfloat162*)&g_w2l[e + 2] = __halves2bfloat162(l2, l3);
    }
}

// ================= aggregation: tiny CTAs (co-resident with GEMM) =========
// 128 threads, ONE node per CTA, 0 smem, low regs. Edge loop unrolled x4 for
// memory-level parallelism. Grid = N_PAD per layer.
__global__ __launch_bounds__(128)
void k_aggr(const float* __restrict__ states_layer, int lout) {
    const int node = blockIdx.x;
    const int t    = threadIdx.x;                 // one float4 column each
    const float4* S = (const float4*)states_layer;

    float4 acc = make_float4(0.f, 0.f, 0.f, 0.f);
    if (node < N_NODES) {
        int beg = g_row_ptr[node];
        int end = g_row_ptr[node + 1];
        int e = beg;
        for (; e + 4 <= end; e += 4) {
            int s0 = g_col[e],     s1 = g_col[e + 1];
            int s2 = g_col[e + 2], s3 = g_col[e + 3];
            float4 v0 = S[(size_t)s0 * (HIDDEN / 4) + t];
            float4 v1 = S[(size_t)s1 * (HIDDEN / 4) + t];
            float4 v2 = S[(size_t)s2 * (HIDDEN / 4) + t];
            float4 v3 = S[(size_t)s3 * (HIDDEN / 4) + t];
            acc.x += v0.x + v1.x + v2.x + v3.x;
            acc.y += v0.y + v1.y + v2.y + v3.y;
            acc.z += v0.z + v1.z + v2.z + v3.z;
            acc.w += v0.w + v1.w + v2.w + v3.w;
        }
        for (; e < end; e++) {
            float4 v = S[(size_t)g_col[e] * (HIDDEN / 4) + t];
            acc.x += v.x; acc.y += v.y; acc.z += v.z; acc.w += v.w;
        }
    }
    size_t o = ((size_t)lout * N_PAD + node) * HIDDEN + t * 4;
    __nv_bfloat16 h0, h1, h2, h3, l0, l1, l2, l3;
    split_bf16(acc.x, h0, l0); split_bf16(acc.y, h1, l1);
    split_bf16(acc.z, h2, l2); split_bf16(acc.w, h3, l3);
    *(__nv_bfloat162*)&g_agh[o]     = __halves2bfloat162(h0, h1);
    *(__nv_bfloat162*)&g_agh[o + 2] = __halves2bfloat162(h2, h3);
    *(__nv_bfloat162*)&g_agl[o]     = __halves2bfloat162(l0, l1);
    *(__nv_bfloat162*)&g_agl[o + 2] = __halves2bfloat162(l2, l3);
}

// ================= mma.sync dual-GEMM + tanh epilogue =================
// CTA tile 128x128x32; 8 warps 2(M)x4(N); warp tile 64x32.
// 2-stage cp.async double buffer = 81920 B SMEM => 2 CTAs/SM.
// __launch_bounds__(296, 2): caps regs at ~110 (HW alloc 112) so that
// 2 GEMM CTAs leave an 8K-register gap per SM for one k_aggr CTA.
#define ROWP 40
#define TE   (128 * ROWP)              // elems per tile = 5120
#define STAGE_E (4 * TE)               // elems per stage = 20480
#define SMEM_BYTES (2 * STAGE_E * 2)   // 81920 B

__device__ __forceinline__ void load_stage(
    uint32_t sbase,
    const __nv_bfloat16* __restrict__ Ah, const __nv_bfloat16* __restrict__ Al,
    const __nv_bfloat16* __restrict__ Bh, const __nv_bfloat16* __restrict__ Bl,
    int bm, int n0, int kof, int astr, int bstr, int tid)
{
#pragma unroll
    for (int j = 0; j < 2; j++) {
        int idx = tid + j * 256;   // 0..511
        int r = idx >> 2;
        int c = idx & 3;
        uint32_t d = sbase + (uint32_t)(r * ROWP + c * 8) * 2;
        size_t ga = (size_t)(bm + r) * astr + kof + c * 8;
        size_t gb = (size_t)(n0 + r) * bstr + kof + c * 8;
        cpa16(d,              Ah + ga);
        cpa16(d + TE * 2,     Al + ga);
        cpa16(d + 2 * TE * 2, Bh + gb);
        cpa16(d + 3 * TE * 2, Bl + gb);
    }
}

__global__ __launch_bounds__(296, 2)
void k_gemm_mma(int layer, int K1, int c1,
                const float* __restrict__ s_old,
                const float* __restrict__ leak,
                float* __restrict__ outp,
                int asel, int osel)
{
    extern __shared__ __nv_bfloat16 smem[];
    const uint32_t sm0 = smem_u32(smem);

    const int tid  = threadIdx.x;
    const int wid  = tid >> 5;
    const int lane = tid & 31;
    const int wm   = wid & 1;       // 0..1 (M)
    const int wn   = wid >> 1;      // 0..3 (N)
    const int bm   = blockIdx.y * 128;
    const int n0   = blockIdx.x * 128;

    // operand pointers from selectors
    const __nv_bfloat16 *a1h, *a1l;
    if (asel == 0)      { a1h = g_xh;  a1l = g_xl;  }
    else if (asel == 1) { a1h = g_o1h; a1l = g_o1l; }
    else                { a1h = g_o2h; a1l = g_o2l; }
    __nv_bfloat16 *oh = nullptr, *ol = nullptr;
    if (osel == 1)      { oh = g_o1h; ol = g_o1l; }
    else if (osel == 2) { oh = g_o2h; ol = g_o2l; }
    const __nv_bfloat16* a2h = g_agh + (size_t)layer * N_PAD * HIDDEN;
    const __nv_bfloat16* a2l = g_agl + (size_t)layer * N_PAD * HIDDEN;
    const size_t w1off = (layer == 0) ? 0 : (size_t)131072 + (size_t)(layer - 1) * 262144;
    const __nv_bfloat16* b1h = g_w1h + w1off;
    const __nv_bfloat16* b1l = g_w1l + w1off;
    const __nv_bfloat16* b2h = g_w2h + (size_t)layer * 262144;
    const __nv_bfloat16* b2l = g_w2l + (size_t)layer * 262144;

    float acc[4][4][4];
#pragma unroll
    for (int i = 0; i < 4; i++)
#pragma unroll
        for (int j = 0; j < 4; j++)
#pragma unroll
            for (int q = 0; q < 4; q++) acc[i][j][q] = 0.f;

    const int ctot = c1 + 16;

    // prologue: stage 0 = phase-1 chunk 0
    load_stage(sm0, a1h, a1l, b1h, b1l, bm, n0, 0, K1, K1, tid);
    CP_COMMIT();

    // ldmatrix lane-address components
    const int arow = (lane & 7) + ((lane >> 3) & 1) * 8;   // + wm*64 + mi*16
    const int acol = (lane >> 4) * 8;                       // + ks*16
    const int brow = (lane & 7) + (lane >> 4) * 8;          // + wn*32 + ng2*16
    const int bcol = ((lane >> 3) & 1) * 8;                 // + ks*16

    for (int ci = 0; ci < ctot; ci++) {
        if (ci + 1 < ctot) {
            int cj = ci + 1;
            uint32_t sb = sm0 + (uint32_t)((cj & 1) * STAGE_E) * 2;
            if (cj < c1)
                load_stage(sb, a1h, a1l, b1h, b1l, bm, n0, cj * 32, K1, K1, tid);
            else
                load_stage(sb, a2h, a2l, b2h, b2l, bm, n0, (cj - c1) * 32,
                           HIDDEN, HIDDEN, tid);
            CP_COMMIT();
            CP_WAIT(1);
        } else {
            CP_WAIT(0);
        }
        __syncthreads();

        const uint32_t sb = sm0 + (uint32_t)((ci & 1) * STAGE_E) * 2;
        const uint32_t aB = sb + (uint32_t)((wm * 64 + arow) * ROWP + acol) * 2;
        const uint32_t bB = sb + (uint32_t)(2 * TE + (wn * 32 + brow) * ROWP + bcol) * 2;

#pragma unroll
        for (int ks = 0; ks < 2; ks++) {
            // staged fragments: af holds A-hi first, then is REUSED for A-lo.
            // Peak live fragment regs: af(16)+bh(8)+bl(8) = 32 (was 48).
            uint32_t af[4][4], bh[4][2], bl[4][2];
#pragma unroll
            for (int g2 = 0; g2 < 2; g2++) {
                uint32_t bd = bB + (uint32_t)(g2 * 16 * ROWP + ks * 16) * 2;
                uint32_t t0, t1, t2, t3;
                LDSM4(t0, t1, t2, t3, bd);
                bh[2 * g2][0] = t0; bh[2 * g2][1] = t1;
                bh[2 * g2 + 1][0] = t2; bh[2 * g2 + 1][1] = t3;
                LDSM4(t0, t1, t2, t3, bd + TE * 2);
                bl[2 * g2][0] = t0; bl[2 * g2][1] = t1;
                bl[2 * g2 + 1][0] = t2; bl[2 * g2 + 1][1] = t3;
            }
#pragma unroll
            for (int mi = 0; mi < 4; mi++) {
                uint32_t ad = aB + (uint32_t)(mi * 16 * ROWP + ks * 16) * 2;
                LDSM4(af[mi][0], af[mi][1], af[mi][2], af[mi][3], ad);
            }
            // hh: Ah * Bh
#pragma unroll
            for (int mi = 0; mi < 4; mi++)
#pragma unroll
                for (int ni = 0; ni < 4; ni++)
                    MMA16816(acc[mi][ni], af[mi][0], af[mi][1], af[mi][2], af[mi][3],
                             bh[ni][0], bh[ni][1]);
            // hl: Ah * Bl
#pragma unroll
            for (int mi = 0; mi < 4; mi++)
#pragma unroll
                for (int ni = 0; ni < 4; ni++)
                    MMA16816(acc[mi][ni], af[mi][0], af[mi][1], af[mi][2], af[mi][3],
                             bl[ni][0], bl[ni][1]);
            // reload A-lo into af, then lh: Al * Bh
#pragma unroll
            for (int mi = 0; mi < 4; mi++) {
                uint32_t ad = aB + (uint32_t)(mi * 16 * ROWP + ks * 16) * 2 + TE * 2;
                LDSM4(af[mi][0], af[mi][1], af[mi][2], af[mi][3], ad);
            }
#pragma unroll
            for (int mi = 0; mi < 4; mi++)
#pragma unroll
                for (int ni = 0; ni < 4; ni++)
                    MMA16816(acc[mi][ni], af[mi][0], af[mi][1], af[mi][2], af[mi][3],
                             bh[ni][0], bh[ni][1]);
        }
        __syncthreads();
    }

    // ---------------- epilogue ----------------
    const float a   = leak[0];
    const float oma = 1.0f - a;
#pragma unroll
    for (int mi = 0; mi < 4; mi++) {
#pragma unroll
        for (int h = 0; h < 2; h++) {
            int mm = bm + wm * 64 + mi * 16 + (lane >> 2) + h * 8;
            bool valid = (mm < N_NODES);
            size_t rowb = (size_t)mm * HIDDEN + n0 + wn * 32 + (lane & 3) * 2;
#pragma unroll
            for (int ni = 0; ni < 4; ni++) {
                size_t off = rowb + ni * 8;
                if (valid) {
                    float c0 = acc[mi][ni][2 * h];
                    float c1 = acc[mi][ni][2 * h + 1];
                    float2 s = *(const float2*)&s_old[off];
                    float o0 = a * fast_tanh(c0) + oma * s.x;
                    float o1 = a * fast_tanh(c1) + oma * s.y;
                    *(float2*)&outp[off] = make_float2(o0, o1);
                    if (oh) {
                        __nv_bfloat16 h0, h1, l0, l1;
                        split_bf16(o0, h0, l0);
                        split_bf16(o1, h1, l1);
                        *(__nv_bfloat162*)&oh[off] = __halves2bfloat162(h0, h1);
                        *(__nv_bfloat162*)&ol[off] = __halves2bfloat162(l0, l1);
                    }
                } else if (oh) {
                    __nv_bfloat162 z =
                        __halves2bfloat162(__float2bfloat16_rn(0.f),
                                           __float2bfloat16_rn(0.f));
                    *(__nv_bfloat162*)&oh[off] = z;
                    *(__nv_bfloat162*)&ol[off] = z;
                }
            }
        }
    }
}

// ================= launch =================
extern "C" void kernel_launch(void* const* d_in, const int* in_sizes, int n_in,
                              void* d_out, int out_size)
{
    const int*   ei      = (const int*)d_in[0];       // [2, E] int32
    const float* x       = (const float*)d_in[1];     // [N, 256]
    const float* states  = (const float*)d_in[2];     // [4, N, 512]
    const float* Wi0     = (const float*)d_in[3];     // [512, 256]
    const float* Wi_rest = (const float*)d_in[4];     // [3, 512, 512]
    const float* Wr      = (const float*)d_in[5];     // [4, 512, 512]
    const float* leak    = (const float*)d_in[6];     // [1]
    float*       out     = (float*)d_out;             // [4, N, 512]

    (void)in_sizes; (void)n_in; (void)out_size;

    static cudaStream_t sAg = nullptr;
    static cudaEvent_t evFork = nullptr;
    static cudaEvent_t evA[NUM_LAYERS];
    if (sAg == nullptr) {
        cudaFuncSetAttribute(k_gemm_mma,
                             cudaFuncAttributeMaxDynamicSharedMemorySize,
                             SMEM_BYTES);
        cudaStreamCreateWithFlags(&sAg, cudaStreamNonBlocking);
        cudaEventCreateWithFlags(&evFork, cudaEventDisableTiming);
        for (int l = 0; l < NUM_LAYERS; l++)
            cudaEventCreateWithFlags(&evA[l], cudaEventDisableTiming);
    }

    // ---- main stream: CSR build ----
    k_zero_deg<<<128, 256>>>();
    k_hist<<<(N_EDGES + 255) / 256, 256>>>(ei);
    k_scan<<<1, 1024>>>();
    k_scatter<<<(N_EDGES + 255) / 256, 256>>>(ei);

    // ---- legal capture fork: event recorded on origin stream ----
    cudaEventRecord(evFork, 0);
    cudaStreamWaitEvent(sAg, evFork, 0);

    // ---- side stream: 4 layer aggregations (tiny CTAs, co-resident) ----
    for (int l = 0; l < NUM_LAYERS; l++) {
        k_aggr<<<N_PAD, 128, 0, sAg>>>(states + (size_t)l * N_NODES * HIDDEN, l);
        cudaEventRecord(evA[l], sAg);
    }

    // ---- main stream: conversions (overlap with aggr0) ----
    k_convert_x<<<4096, 256>>>(x);
    k_convert_w<<<1024, 256>>>(Wi0, Wi_rest, Wr);

    // ---- main stream: sequential GEMM chain; GEMM l waits on aggr l ----
    dim3 grid(HIDDEN / 128, MTILES);
    const int asel[4] = {0, 1, 2, 1};
    const int osel[4] = {1, 2, 1, 0};
    for (int l = 0; l < NUM_LAYERS; l++) {
        int K1 = (l == 0) ? IN_FEAT : HIDDEN;
        int c1 = K1 / 32;
        const float* so = states + (size_t)l * N_NODES * HIDDEN;
        float*       ol = out + (size_t)l * N_NODES * HIDDEN;
        cudaStreamWaitEvent(0, evA[l], 0);
        k_gemm_mma<<<grid, 256, SMEM_BYTES>>>(l, K1, c1, so, leak, ol,
                                              asel[l], osel[l]);
    }
}